// round 2
// baseline (speedup 1.0000x reference)
#include <cuda_runtime.h>
#include <math.h>

// Problem constants
#define Bc  8
#define Tc  1024
#define Dc  768
#define NEc 8
#define DSc 128
#define Hc  64

// ---------------------------------------------------------------------------
// Scratch (static __device__ arrays — no allocation at runtime)
// ---------------------------------------------------------------------------
__device__ float g_Wit[768 * 128];      // Wi^T            [768,128]
__device__ float g_Wiht[128 * 384];     // W_ih^T          [128,384]
__device__ float g_Wmt[128 * 768];      // Wm^T            [128,768]
__device__ float g_Wst[6144 * 768];     // Ws^T            [6144,768]
__device__ float g_Whcat[128 * 192];    // [Wh1;Wt1;Wv1]^T [128,192]
__device__ float g_bhcat[192];
__device__ float g_proj[8192 * 128];    // h_seq @ Wi^T + bi
__device__ float g_gp[8192 * 384];      // proj @ W_ih^T (no bias)
__device__ float g_Cp[1024 * 768];      // combined pooled weight [NE*DS, D]
__device__ float g_bpool[768];          // combined pooled bias
__device__ float g_hdn[65536 * 192];    // head layer-1 pre-GELU

// ---------------------------------------------------------------------------
// Generic transpose: out[C,R] = in[R,C]^T
// ---------------------------------------------------------------------------
__global__ void transpose_k(const float* __restrict__ in, float* __restrict__ out,
                            int R, int C)
{
    __shared__ float t[32][33];
    int c0 = blockIdx.x * 32, r0 = blockIdx.y * 32;
#pragma unroll
    for (int i = 0; i < 4; i++) {
        int r = r0 + threadIdx.y + i * 8;
        int c = c0 + threadIdx.x;
        if (r < R && c < C) t[threadIdx.y + i * 8][threadIdx.x] = in[(size_t)r * C + c];
    }
    __syncthreads();
#pragma unroll
    for (int i = 0; i < 4; i++) {
        int c = c0 + threadIdx.y + i * 8;
        int r = r0 + threadIdx.x;
        if (r < R && c < C) out[(size_t)c * R + r] = t[threadIdx.x][threadIdx.y + i * 8];
    }
}

// ---------------------------------------------------------------------------
// Concatenate head layer-1 weights (transposed) and biases
// ---------------------------------------------------------------------------
__global__ void headscat_k(const float* __restrict__ Wh1, const float* __restrict__ Wt1,
                           const float* __restrict__ Wv1, const float* __restrict__ bh1,
                           const float* __restrict__ bt1, const float* __restrict__ bv1,
                           float* __restrict__ Wcat, float* __restrict__ bcat)
{
    int idx = blockIdx.x * 256 + threadIdx.x;
    if (idx < 128 * 192) {
        int k = idx / 192, col = idx - k * 192;
        int h = col >> 6, n = col & 63;
        const float* W = (h == 0) ? Wh1 : (h == 1 ? Wt1 : Wv1);
        Wcat[idx] = W[n * 128 + k];
    }
    if (idx < 192) {
        int h = idx >> 6, n = idx & 63;
        const float* bb = (h == 0) ? bh1 : (h == 1 ? bt1 : bv1);
        bcat[idx] = bb[n];
    }
}

// ---------------------------------------------------------------------------
// Routing: logits + softmax over NE=8.  One warp per (b,t) row.
// ---------------------------------------------------------------------------
__global__ __launch_bounds__(256) void route_k(const float* __restrict__ h_seq,
                                               const float* __restrict__ keys,
                                               float* __restrict__ rw)
{
    __shared__ float4 ks[8 * 192];  // 8 keys x 768 floats
    int tid = threadIdx.x;
    const float4* k4 = (const float4*)keys;
    for (int i = tid; i < 1536; i += 256) ks[i] = k4[i];
    __syncthreads();

    int r = blockIdx.x * 8 + (tid >> 5);
    int lane = tid & 31;
    const float4* h4 = (const float4*)h_seq + (size_t)r * 192;
    float acc[8];
#pragma unroll
    for (int e = 0; e < 8; e++) acc[e] = 0.f;
#pragma unroll
    for (int i = 0; i < 6; i++) {
        float4 hv = h4[i * 32 + lane];
#pragma unroll
        for (int e = 0; e < 8; e++) {
            float4 kv = ks[e * 192 + i * 32 + lane];
            acc[e] += hv.x * kv.x + hv.y * kv.y + hv.z * kv.z + hv.w * kv.w;
        }
    }
#pragma unroll
    for (int e = 0; e < 8; e++)
#pragma unroll
        for (int s = 16; s; s >>= 1) acc[e] += __shfl_xor_sync(0xffffffffu, acc[e], s);

    if (lane == 0) {
        const float inv = 1.0f / 27.712812921102035f;  // 1/(sqrt(768)*1.0)
        float m = -1e30f;
#pragma unroll
        for (int e = 0; e < 8; e++) { acc[e] *= inv; m = fmaxf(m, acc[e]); }
        float s = 0.f;
#pragma unroll
        for (int e = 0; e < 8; e++) { acc[e] = expf(acc[e] - m); s += acc[e]; }
        float is = 1.f / s;
#pragma unroll
        for (int e = 0; e < 8; e++) rw[(size_t)r * 8 + e] = acc[e] * is;
    }
}

// ---------------------------------------------------------------------------
// Combined pooled bias: bpool[d] = bs[d] + sum_{e,j} bm[j] * Ws[d, e*768+j]
// ---------------------------------------------------------------------------
__global__ void bpool_k(const float* __restrict__ Ws, const float* __restrict__ bm,
                        const float* __restrict__ bs, float* __restrict__ bp)
{
    __shared__ float red[256];
    int d = blockIdx.x;
    const float* row = Ws + (size_t)d * 6144;
    float acc = 0.f;
    for (int e = 0; e < 8; e++)
        for (int j = threadIdx.x; j < 768; j += 256)
            acc += row[e * 768 + j] * bm[j];
    red[threadIdx.x] = acc;
    __syncthreads();
    for (int s = 128; s; s >>= 1) {
        if (threadIdx.x < s) red[threadIdx.x] += red[threadIdx.x + s];
        __syncthreads();
    }
    if (threadIdx.x == 0) bp[d] = bs[d] + red[0];
}

// ---------------------------------------------------------------------------
// Generic SGEMM: C[M,N] = A[M,K] @ B[K,N] (+ bias[N]).  64x64x16 tiles,
// 256 threads, 4x4 per-thread, register-prefetched global loads.
// All dims assumed divisible (64 | M,N ; 16 | K) — true for every call here.
// Batched via blockIdx.z with element strides.
// ---------------------------------------------------------------------------
__global__ __launch_bounds__(256) void sgemm_k(
    const float* __restrict__ A, const float* __restrict__ B,
    const float* __restrict__ bias, float* __restrict__ C,
    int M, int N, int K, long long aBS, long long bBS, long long cBS)
{
    A += (size_t)blockIdx.z * aBS;
    B += (size_t)blockIdx.z * bBS;
    C += (size_t)blockIdx.z * cBS;

    __shared__ float As[16][68];
    __shared__ float Bs[16][64];
    int tid = threadIdx.x;
    int m0 = blockIdx.y * 64, n0 = blockIdx.x * 64;
    int ar = tid >> 2, ac = (tid & 3) << 2;
    int br = tid >> 4, bc = (tid & 15) << 2;
    int tx = tid & 15, ty = tid >> 4;

    float acc[4][4];
#pragma unroll
    for (int i = 0; i < 4; i++)
#pragma unroll
        for (int j = 0; j < 4; j++) acc[i][j] = 0.f;

    const float* Ap = A + (size_t)(m0 + ar) * K + ac;
    const float* Bp = B + (size_t)br * N + n0 + bc;
    int nk = K >> 4;
    float4 a4 = *(const float4*)Ap;
    float4 b4 = *(const float4*)Bp;

    for (int kt = 0; kt < nk; ++kt) {
        As[ac + 0][ar] = a4.x; As[ac + 1][ar] = a4.y;
        As[ac + 2][ar] = a4.z; As[ac + 3][ar] = a4.w;
        *(float4*)&Bs[br][bc] = b4;
        __syncthreads();
        if (kt + 1 < nk) {
            a4 = *(const float4*)(Ap + (kt + 1) * 16);
            b4 = *(const float4*)(Bp + (size_t)(kt + 1) * 16 * N);
        }
#pragma unroll
        for (int k = 0; k < 16; ++k) {
            float4 av = *(const float4*)&As[k][ty << 2];
            float4 bv = *(const float4*)&Bs[k][tx << 2];
            float am[4] = {av.x, av.y, av.z, av.w};
            float bn[4] = {bv.x, bv.y, bv.z, bv.w};
#pragma unroll
            for (int i = 0; i < 4; i++)
#pragma unroll
                for (int j = 0; j < 4; j++)
                    acc[i][j] = fmaf(am[i], bn[j], acc[i][j]);
        }
        __syncthreads();
    }

    float4 bb = make_float4(0.f, 0.f, 0.f, 0.f);
    if (bias) bb = *(const float4*)&bias[n0 + (tx << 2)];
#pragma unroll
    for (int i = 0; i < 4; i++) {
        float4 o;
        o.x = acc[i][0] + bb.x; o.y = acc[i][1] + bb.y;
        o.z = acc[i][2] + bb.z; o.w = acc[i][3] + bb.w;
        *(float4*)&C[(size_t)(m0 + (ty << 2) + i) * N + n0 + (tx << 2)] = o;
    }
}

// ---------------------------------------------------------------------------
// GRU scan: one CTA per (b,e) lane, 384 threads (one per gate row).
// W_hh resident in SMEM, XOR-swizzled so per-row float4 reads are phase-
// conflict-free.  gi reconstructed as route_w * gp + b_ih (linearity).
// ---------------------------------------------------------------------------
__global__ __launch_bounds__(384) void gru_k(
    const float* __restrict__ gp, const float* __restrict__ rw,
    const float* __restrict__ Whh, const float* __restrict__ b_ih,
    const float* __restrict__ b_hh, const float* __restrict__ state0,
    float* __restrict__ state_out)
{
    extern __shared__ float sm[];
    float4* swW = (float4*)sm;              // 12288 float4 (196608 B)
    float* h_s  = sm + 49152;               // 128
    float* sA   = h_s + 128;                // 384
    float* sHn  = sA + 384;                 // 128

    int tid = threadIdx.x;
    int L = blockIdx.x;
    int b = L >> 3, e = L & 7;

    // Load W_hh with swizzle: row o, float4 j stored at slot j ^ (o & 7)
    const float4* Whh4 = (const float4*)Whh;
    for (int idx = tid; idx < 12288; idx += 384) {
        int o = idx >> 5, j = idx & 31;
        swW[(o << 5) | (j ^ (o & 7))] = Whh4[idx];
    }
    if (tid < 128) h_s[tid] = state0[(e << 7) + tid];
    float bihr = b_ih[tid];
    float bhhr = b_hh[tid];
    int base = tid << 5, sw = tid & 7;
    size_t gpBase = ((size_t)b * Tc) * 384 + tid;
    size_t rwBase = ((size_t)b * Tc) * 8 + e;
    size_t soBase = (((size_t)b * Tc) * 8 + e) * 128;
    __syncthreads();

    const float4* h4 = (const float4*)h_s;
    float gpc = gp[gpBase];
    float rwc = rw[rwBase];

    for (int t = 0; t < Tc; ++t) {
        float gpn = 0.f, rwn = 0.f;
        if (t + 1 < Tc) {
            gpn = gp[gpBase + (size_t)(t + 1) * 384];
            rwn = rw[rwBase + (size_t)(t + 1) * 8];
        }
        float acc = bhhr;
#pragma unroll
        for (int j = 0; j < 32; ++j) {
            float4 w = swW[base + (j ^ sw)];
            float4 hv = h4[j];
            acc = fmaf(w.x, hv.x, acc);
            acc = fmaf(w.y, hv.y, acc);
            acc = fmaf(w.z, hv.z, acc);
            acc = fmaf(w.w, hv.w, acc);
        }
        float gi = fmaf(rwc, gpc, bihr);
        if (tid < 256) sA[tid] = gi + acc;
        else { sA[tid] = gi; sHn[tid - 256] = acc; }
        __syncthreads();
        if (tid < 128) {
            float r = 1.f / (1.f + expf(-sA[tid]));
            float z = 1.f / (1.f + expf(-sA[128 + tid]));
            float n = tanhf(fmaf(r, sHn[tid], sA[256 + tid]));
            float hold = h_s[tid];
            float hn = fmaf(z, hold - n, n);
            h_s[tid] = hn;
            state_out[soBase + (size_t)t * 1024 + tid] = hn;
        }
        __syncthreads();
        gpc = gpn; rwc = rwn;
    }
}

// ---------------------------------------------------------------------------
// Head layer 2: GELU(exact) + 64->1 dot, one warp per (row, head)
// ---------------------------------------------------------------------------
__global__ __launch_bounds__(256) void heads_l2_k(
    const float* __restrict__ hdn,
    const float* __restrict__ Wh2, const float* __restrict__ bh2,
    const float* __restrict__ Wt2, const float* __restrict__ bt2,
    const float* __restrict__ Wv2, const float* __restrict__ bv2,
    float* __restrict__ oh, float* __restrict__ ot, float* __restrict__ ov)
{
    int task = blockIdx.x * 8 + (threadIdx.x >> 5);
    int lane = threadIdx.x & 31;
    int row = task / 3, h = task - row * 3;
    const float* W2 = (h == 0) ? Wh2 : (h == 1 ? Wt2 : Wv2);
    const float* b2 = (h == 0) ? bh2 : (h == 1 ? bt2 : bv2);
    const float* x = hdn + (size_t)row * 192 + h * 64;
    float x1 = x[lane], x2 = x[lane + 32];
    float g1 = 0.5f * x1 * (1.f + erff(x1 * 0.7071067811865476f));
    float g2 = 0.5f * x2 * (1.f + erff(x2 * 0.7071067811865476f));
    float acc = g1 * W2[lane] + g2 * W2[lane + 32];
#pragma unroll
    for (int s = 16; s; s >>= 1) acc += __shfl_xor_sync(0xffffffffu, acc, s);
    if (lane == 0) {
        float* o = (h == 0) ? oh : (h == 1 ? ot : ov);
        o[row] = acc + b2[0];
    }
}

// ---------------------------------------------------------------------------
// Launch
// ---------------------------------------------------------------------------
extern "C" void kernel_launch(void* const* d_in, const int* in_sizes, int n_in,
                              void* d_out, int out_size)
{
    const float* h_seq = (const float*)d_in[0];
    const float* keys  = (const float*)d_in[1];
    const float* state0= (const float*)d_in[2];
    const float* Wi    = (const float*)d_in[3];
    const float* bi    = (const float*)d_in[4];
    const float* W_ih  = (const float*)d_in[5];
    const float* W_hh  = (const float*)d_in[6];
    const float* b_ih  = (const float*)d_in[7];
    const float* b_hh  = (const float*)d_in[8];
    const float* Wm    = (const float*)d_in[9];
    const float* bm    = (const float*)d_in[10];
    const float* Ws    = (const float*)d_in[11];
    const float* bs    = (const float*)d_in[12];
    const float* Wh1   = (const float*)d_in[13];
    const float* bh1   = (const float*)d_in[14];
    const float* Wh2   = (const float*)d_in[15];
    const float* bh2   = (const float*)d_in[16];
    const float* Wt1   = (const float*)d_in[17];
    const float* bt1   = (const float*)d_in[18];
    const float* Wt2   = (const float*)d_in[19];
    const float* bt2   = (const float*)d_in[20];
    const float* Wv1   = (const float*)d_in[21];
    const float* bv1   = (const float*)d_in[22];
    const float* Wv2   = (const float*)d_in[23];
    const float* bv2   = (const float*)d_in[24];

    float* out = (float*)d_out;
    float* o_pooled = out;                                     // [8,1024,768]
    float* o_mem    = o_pooled + (size_t)8192 * 768;           // [8,1024,8,768]
    float* o_state  = o_mem + (size_t)65536 * 768;             // [8,1024,8,128]
    float* o_holder = o_state + (size_t)65536 * 128;           // [8,1024,8]
    float* o_tagged = o_holder + 65536;
    float* o_visib  = o_tagged + 65536;
    float* o_route  = o_visib + 65536;

    float *p_Wit, *p_Wiht, *p_Wmt, *p_Wst, *p_Whcat, *p_bhcat;
    float *p_proj, *p_gp, *p_Cp, *p_bpool, *p_hdn;
    cudaGetSymbolAddress((void**)&p_Wit,   g_Wit);
    cudaGetSymbolAddress((void**)&p_Wiht,  g_Wiht);
    cudaGetSymbolAddress((void**)&p_Wmt,   g_Wmt);
    cudaGetSymbolAddress((void**)&p_Wst,   g_Wst);
    cudaGetSymbolAddress((void**)&p_Whcat, g_Whcat);
    cudaGetSymbolAddress((void**)&p_bhcat, g_bhcat);
    cudaGetSymbolAddress((void**)&p_proj,  g_proj);
    cudaGetSymbolAddress((void**)&p_gp,    g_gp);
    cudaGetSymbolAddress((void**)&p_Cp,    g_Cp);
    cudaGetSymbolAddress((void**)&p_bpool, g_bpool);
    cudaGetSymbolAddress((void**)&p_hdn,   g_hdn);

    dim3 tb(32, 8);
    // Weight prep
    transpose_k<<<dim3(24, 4),  tb>>>(Wi,   p_Wit,  128, 768);
    transpose_k<<<dim3(4, 12),  tb>>>(W_ih, p_Wiht, 384, 128);
    transpose_k<<<dim3(4, 24),  tb>>>(Wm,   p_Wmt,  768, 128);
    transpose_k<<<dim3(192, 24), tb>>>(Ws,  p_Wst,  768, 6144);
    headscat_k<<<96, 256>>>(Wh1, Wt1, Wv1, bh1, bt1, bv1, p_Whcat, p_bhcat);

    // Routing (writes route_weights output, consumed by GRU)
    route_k<<<1024, 256>>>(h_seq, keys, o_route);

    // proj = h_seq @ Wi^T + bi           [8192,128]
    sgemm_k<<<dim3(2, 128), 256>>>(h_seq, p_Wit, bi, p_proj, 8192, 128, 768, 0, 0, 0);
    // gp = proj @ W_ih^T (no bias)       [8192,384]
    sgemm_k<<<dim3(6, 128), 256>>>(p_proj, p_Wiht, nullptr, p_gp, 8192, 384, 128, 0, 0, 0);
    // Cp[e] = Wm^T @ Ws_e^T              [1024,768] (batched over e)
    sgemm_k<<<dim3(12, 2, 8), 256>>>(p_Wmt, p_Wst, nullptr, p_Cp,
                                     128, 768, 768, 0, 589824, 98304);
    bpool_k<<<768, 256>>>(Ws, bm, bs, p_bpool);

    // GRU scan (sequential over T) -> state_stack output
    cudaFuncSetAttribute(gru_k, cudaFuncAttributeMaxDynamicSharedMemorySize, 199168);
    gru_k<<<64, 384, 199168>>>(p_gp, o_route, W_hh, b_ih, b_hh, state0, o_state);

    // memory_stack = state @ Wm^T + bm   [65536,768]
    sgemm_k<<<dim3(12, 1024), 256>>>(o_state, p_Wmt, bm, o_mem, 65536, 768, 128, 0, 0, 0);
    // heads layer-1 (3 heads fused)      [65536,192]
    sgemm_k<<<dim3(3, 1024), 256>>>(o_state, p_Whcat, p_bhcat, p_hdn, 65536, 192, 128, 0, 0, 0);
    heads_l2_k<<<24576, 256>>>(p_hdn, Wh2, bh2, Wt2, bt2, Wv2, bv2,
                               o_holder, o_tagged, o_visib);
    // pooled = state.reshape(8192,1024) @ Cp + bpool   [8192,768]
    sgemm_k<<<dim3(12, 128), 256>>>(o_state, p_Cp, p_bpool, o_pooled, 8192, 768, 1024, 0, 0, 0);
}

// round 3
// speedup vs baseline: 1.1885x; 1.1885x over previous
#include <cuda_runtime.h>
#include <math.h>

// Problem constants
#define Bc  8
#define Tc  1024
#define Dc  768
#define NEc 8
#define DSc 128
#define Hc  64

// ---------------------------------------------------------------------------
// Scratch (static __device__ arrays — no allocation at runtime)
// ---------------------------------------------------------------------------
__device__ float g_Wit[768 * 128];      // Wi^T            [768,128]
__device__ float g_Wiht[128 * 384];     // W_ih^T          [128,384]
__device__ float g_Wmt[128 * 768];      // Wm^T            [128,768]
__device__ float g_Wst[6144 * 768];     // Ws^T            [6144,768]
__device__ float g_Whr[192 * 128];      // [Wh1;Wt1;Wv1] row-concat [192,128]
__device__ float g_bhcat[192];
__device__ float g_proj[8192 * 128];    // h_seq @ Wi^T + bi
__device__ float g_gp[8192 * 384];      // proj @ W_ih^T (no bias)
__device__ float g_Cp[1024 * 768];      // combined pooled weight [NE*DS, D]
__device__ float g_Cpt[768 * 1024];     // Cp^T  [D, NE*DS]
__device__ float g_bpool[768];          // combined pooled bias
__device__ float g_hdn[65536 * 192];    // head layer-1 pre-GELU

// ---------------------------------------------------------------------------
// Generic transpose: out[C,R] = in[R,C]^T
// ---------------------------------------------------------------------------
__global__ void transpose_k(const float* __restrict__ in, float* __restrict__ out,
                            int R, int C)
{
    __shared__ float t[32][33];
    int c0 = blockIdx.x * 32, r0 = blockIdx.y * 32;
#pragma unroll
    for (int i = 0; i < 4; i++) {
        int r = r0 + threadIdx.y + i * 8;
        int c = c0 + threadIdx.x;
        if (r < R && c < C) t[threadIdx.y + i * 8][threadIdx.x] = in[(size_t)r * C + c];
    }
    __syncthreads();
#pragma unroll
    for (int i = 0; i < 4; i++) {
        int c = c0 + threadIdx.y + i * 8;
        int r = r0 + threadIdx.x;
        if (r < R && c < C) out[(size_t)c * R + r] = t[threadIdx.x][threadIdx.y + i * 8];
    }
}

// ---------------------------------------------------------------------------
// Row-concat head layer-1 weights [192,128] and biases [192]
// ---------------------------------------------------------------------------
__global__ void headscat_k(const float* __restrict__ Wh1, const float* __restrict__ Wt1,
                           const float* __restrict__ Wv1, const float* __restrict__ bh1,
                           const float* __restrict__ bt1, const float* __restrict__ bv1,
                           float* __restrict__ Wr, float* __restrict__ bcat)
{
    int idx = blockIdx.x * 256 + threadIdx.x;
    if (idx < 24576) {
        const float* src = (idx < 8192) ? Wh1 : (idx < 16384 ? Wt1 : Wv1);
        Wr[idx] = src[idx & 8191];
    }
    if (idx < 192) {
        int h = idx >> 6, n = idx & 63;
        const float* bb = (h == 0) ? bh1 : (h == 1 ? bt1 : bv1);
        bcat[idx] = bb[n];
    }
}

// ---------------------------------------------------------------------------
// Routing: logits + softmax over NE=8.  One warp per (b,t) row.
// ---------------------------------------------------------------------------
__global__ __launch_bounds__(256) void route_k(const float* __restrict__ h_seq,
                                               const float* __restrict__ keys,
                                               float* __restrict__ rw)
{
    __shared__ float4 ks[8 * 192];  // 8 keys x 768 floats
    int tid = threadIdx.x;
    const float4* k4 = (const float4*)keys;
    for (int i = tid; i < 1536; i += 256) ks[i] = k4[i];
    __syncthreads();

    int r = blockIdx.x * 8 + (tid >> 5);
    int lane = tid & 31;
    const float4* h4 = (const float4*)h_seq + (size_t)r * 192;
    float acc[8];
#pragma unroll
    for (int e = 0; e < 8; e++) acc[e] = 0.f;
#pragma unroll
    for (int i = 0; i < 6; i++) {
        float4 hv = h4[i * 32 + lane];
#pragma unroll
        for (int e = 0; e < 8; e++) {
            float4 kv = ks[e * 192 + i * 32 + lane];
            acc[e] += hv.x * kv.x + hv.y * kv.y + hv.z * kv.z + hv.w * kv.w;
        }
    }
#pragma unroll
    for (int e = 0; e < 8; e++)
#pragma unroll
        for (int s = 16; s; s >>= 1) acc[e] += __shfl_xor_sync(0xffffffffu, acc[e], s);

    if (lane == 0) {
        const float inv = 1.0f / 27.712812921102035f;  // 1/(sqrt(768)*1.0)
        float m = -1e30f;
#pragma unroll
        for (int e = 0; e < 8; e++) { acc[e] *= inv; m = fmaxf(m, acc[e]); }
        float s = 0.f;
#pragma unroll
        for (int e = 0; e < 8; e++) { acc[e] = expf(acc[e] - m); s += acc[e]; }
        float is = 1.f / s;
#pragma unroll
        for (int e = 0; e < 8; e++) rw[(size_t)r * 8 + e] = acc[e] * is;
    }
}

// ---------------------------------------------------------------------------
// Combined pooled bias: bpool[d] = bs[d] + sum_{e,j} bm[j] * Ws[d, e*768+j]
// ---------------------------------------------------------------------------
__global__ void bpool_k(const float* __restrict__ Ws, const float* __restrict__ bm,
                        const float* __restrict__ bs, float* __restrict__ bp)
{
    __shared__ float red[256];
    int d = blockIdx.x;
    const float* row = Ws + (size_t)d * 6144;
    float acc = 0.f;
    for (int e = 0; e < 8; e++)
        for (int j = threadIdx.x; j < 768; j += 256)
            acc += row[e * 768 + j] * bm[j];
    red[threadIdx.x] = acc;
    __syncthreads();
    for (int s = 128; s; s >>= 1) {
        if (threadIdx.x < s) red[threadIdx.x] += red[threadIdx.x + s];
        __syncthreads();
    }
    if (threadIdx.x == 0) bp[d] = bs[d] + red[0];
}

// ---------------------------------------------------------------------------
// fp32 SGEMM (kept for the scan-feeding GEMMs to preserve fp32 state accuracy)
// C[M,N] = A[M,K] @ B[K,N] (+ bias[N]).  64x64x16 tiles.
// ---------------------------------------------------------------------------
__global__ __launch_bounds__(256) void sgemm_k(
    const float* __restrict__ A, const float* __restrict__ B,
    const float* __restrict__ bias, float* __restrict__ C,
    int M, int N, int K, long long aBS, long long bBS, long long cBS)
{
    A += (size_t)blockIdx.z * aBS;
    B += (size_t)blockIdx.z * bBS;
    C += (size_t)blockIdx.z * cBS;

    __shared__ float As[16][68];
    __shared__ float Bs[16][64];
    int tid = threadIdx.x;
    int m0 = blockIdx.y * 64, n0 = blockIdx.x * 64;
    int ar = tid >> 2, ac = (tid & 3) << 2;
    int br = tid >> 4, bc = (tid & 15) << 2;
    int tx = tid & 15, ty = tid >> 4;

    float acc[4][4];
#pragma unroll
    for (int i = 0; i < 4; i++)
#pragma unroll
        for (int j = 0; j < 4; j++) acc[i][j] = 0.f;

    const float* Ap = A + (size_t)(m0 + ar) * K + ac;
    const float* Bp = B + (size_t)br * N + n0 + bc;
    int nk = K >> 4;
    float4 a4 = *(const float4*)Ap;
    float4 b4 = *(const float4*)Bp;

    for (int kt = 0; kt < nk; ++kt) {
        As[ac + 0][ar] = a4.x; As[ac + 1][ar] = a4.y;
        As[ac + 2][ar] = a4.z; As[ac + 3][ar] = a4.w;
        *(float4*)&Bs[br][bc] = b4;
        __syncthreads();
        if (kt + 1 < nk) {
            a4 = *(const float4*)(Ap + (kt + 1) * 16);
            b4 = *(const float4*)(Bp + (size_t)(kt + 1) * 16 * N);
        }
#pragma unroll
        for (int k = 0; k < 16; ++k) {
            float4 av = *(const float4*)&As[k][ty << 2];
            float4 bv = *(const float4*)&Bs[k][tx << 2];
            float am[4] = {av.x, av.y, av.z, av.w};
            float bn[4] = {bv.x, bv.y, bv.z, bv.w};
#pragma unroll
            for (int i = 0; i < 4; i++)
#pragma unroll
                for (int j = 0; j < 4; j++)
                    acc[i][j] = fmaf(am[i], bn[j], acc[i][j]);
        }
        __syncthreads();
    }

    float4 bb = make_float4(0.f, 0.f, 0.f, 0.f);
    if (bias) bb = *(const float4*)&bias[n0 + (tx << 2)];
#pragma unroll
    for (int i = 0; i < 4; i++) {
        float4 o;
        o.x = acc[i][0] + bb.x; o.y = acc[i][1] + bb.y;
        o.z = acc[i][2] + bb.z; o.w = acc[i][3] + bb.w;
        *(float4*)&C[(size_t)(m0 + (ty << 2) + i) * N + n0 + (tx << 2)] = o;
    }
}

// ---------------------------------------------------------------------------
// TF32 tensor-core GEMM: C[M,N] = A[M,K](row, lda) @ W[N,K]^T (+bias[N])
// 128x64 CTA tile, BK=32, 8 warps (4m x 2n), m16n8k8 tf32 MMA.
// Smem rows padded to 36 floats -> fragment LDS is conflict-free (4g+tg).
// Requires 128|M, 64|N, 32|K.  Batched over blockIdx.z via aOff/cOff.
// ---------------------------------------------------------------------------
__device__ __forceinline__ float4 cvt_tf32_4(float4 v)
{
    float4 r;
    asm("cvt.rna.tf32.f32 %0, %1;" : "=f"(r.x) : "f"(v.x));
    asm("cvt.rna.tf32.f32 %0, %1;" : "=f"(r.y) : "f"(v.y));
    asm("cvt.rna.tf32.f32 %0, %1;" : "=f"(r.z) : "f"(v.z));
    asm("cvt.rna.tf32.f32 %0, %1;" : "=f"(r.w) : "f"(v.w));
    return r;
}

__device__ __forceinline__ void mma_tf32(float* c, const unsigned* a, const unsigned* b)
{
    asm volatile(
        "mma.sync.aligned.m16n8k8.row.col.f32.tf32.tf32.f32 "
        "{%0,%1,%2,%3}, {%4,%5,%6,%7}, {%8,%9}, {%0,%1,%2,%3};"
        : "+f"(c[0]), "+f"(c[1]), "+f"(c[2]), "+f"(c[3])
        : "r"(a[0]), "r"(a[1]), "r"(a[2]), "r"(a[3]), "r"(b[0]), "r"(b[1]));
}

#define TFPAD 36
#define TF_STAGE (128 * TFPAD + 64 * TFPAD)   // 6912 floats per stage

__global__ __launch_bounds__(256) void gemm_tf32_k(
    const float* __restrict__ A, const float* __restrict__ W,
    const float* __restrict__ bias, float* __restrict__ C,
    int M, int N, int K, int lda, int ldc,
    long long aOff, long long cOff)
{
    extern __shared__ float sm[];
    A += (size_t)blockIdx.z * aOff;
    C += (size_t)blockIdx.z * cOff;

    const int tid = threadIdx.x;
    const int wid = tid >> 5, lane = tid & 31;
    const int g = lane >> 2, tg = lane & 3;
    const int mB = (wid & 3) << 5, nB = (wid >> 2) << 5;
    const int m0 = blockIdx.y << 7, n0 = blockIdx.x << 6;

    const int arow = tid >> 3, acol = (tid & 7) << 2;
    const float* Ag = A + (size_t)(m0 + arow) * lda + acol;
    const float* Wg = W + (size_t)(n0 + arow) * K + acol;

    float acc[2][4][4];
#pragma unroll
    for (int i = 0; i < 2; i++)
#pragma unroll
        for (int j = 0; j < 4; j++)
#pragma unroll
            for (int l = 0; l < 4; l++) acc[i][j][l] = 0.f;

    float4 aR[4], wR[2];
#pragma unroll
    for (int i = 0; i < 4; i++) aR[i] = *(const float4*)(Ag + (size_t)i * 32 * lda);
#pragma unroll
    for (int i = 0; i < 2; i++) wR[i] = *(const float4*)(Wg + (size_t)i * 32 * K);

    {
        float* As = sm;
        float* Bs = sm + 128 * TFPAD;
#pragma unroll
        for (int i = 0; i < 4; i++)
            *(float4*)&As[(arow + i * 32) * TFPAD + acol] = cvt_tf32_4(aR[i]);
#pragma unroll
        for (int i = 0; i < 2; i++)
            *(float4*)&Bs[(arow + i * 32) * TFPAD + acol] = cvt_tf32_4(wR[i]);
    }
    __syncthreads();

    const int nk = K >> 5;
    for (int kc = 0; kc < nk; ++kc) {
        if (kc + 1 < nk) {
            const float* Ag2 = Ag + (kc + 1) * 32;
            const float* Wg2 = Wg + (kc + 1) * 32;
#pragma unroll
            for (int i = 0; i < 4; i++) aR[i] = *(const float4*)(Ag2 + (size_t)i * 32 * lda);
#pragma unroll
            for (int i = 0; i < 2; i++) wR[i] = *(const float4*)(Wg2 + (size_t)i * 32 * K);
        }

        const float* As = sm + (kc & 1) * TF_STAGE;
        const float* Bs = As + 128 * TFPAD;
#pragma unroll
        for (int kf = 0; kf < 4; ++kf) {
            const int kk = (kf << 3) + tg;
            unsigned a[2][4], b[4][2];
#pragma unroll
            for (int mf = 0; mf < 2; ++mf) {
                int r = mB + (mf << 4) + g;
                a[mf][0] = __float_as_uint(As[r * TFPAD + kk]);
                a[mf][1] = __float_as_uint(As[(r + 8) * TFPAD + kk]);
                a[mf][2] = __float_as_uint(As[r * TFPAD + kk + 4]);
                a[mf][3] = __float_as_uint(As[(r + 8) * TFPAD + kk + 4]);
            }
#pragma unroll
            for (int nf = 0; nf < 4; ++nf) {
                int n = nB + (nf << 3) + g;
                b[nf][0] = __float_as_uint(Bs[n * TFPAD + kk]);
                b[nf][1] = __float_as_uint(Bs[n * TFPAD + kk + 4]);
            }
#pragma unroll
            for (int mf = 0; mf < 2; ++mf)
#pragma unroll
                for (int nf = 0; nf < 4; ++nf)
                    mma_tf32(acc[mf][nf], a[mf], b[nf]);
        }

        if (kc + 1 < nk) {
            float* Ad = sm + ((kc + 1) & 1) * TF_STAGE;
            float* Bd = Ad + 128 * TFPAD;
#pragma unroll
            for (int i = 0; i < 4; i++)
                *(float4*)&Ad[(arow + i * 32) * TFPAD + acol] = cvt_tf32_4(aR[i]);
#pragma unroll
            for (int i = 0; i < 2; i++)
                *(float4*)&Bd[(arow + i * 32) * TFPAD + acol] = cvt_tf32_4(wR[i]);
            __syncthreads();
        }
    }

    // Epilogue: float2 stores (c0,c1) and (c2,c3)
#pragma unroll
    for (int mf = 0; mf < 2; ++mf)
#pragma unroll
        for (int nf = 0; nf < 4; ++nf) {
            int row = m0 + mB + (mf << 4) + g;
            int col = n0 + nB + (nf << 3) + (tg << 1);
            float2 bb = make_float2(0.f, 0.f);
            if (bias) bb = *(const float2*)&bias[col];
            float2 v;
            v.x = acc[mf][nf][0] + bb.x;
            v.y = acc[mf][nf][1] + bb.y;
            *(float2*)&C[(size_t)row * ldc + col] = v;
            v.x = acc[mf][nf][2] + bb.x;
            v.y = acc[mf][nf][3] + bb.y;
            *(float2*)&C[(size_t)(row + 8) * ldc + col] = v;
        }
}

// ---------------------------------------------------------------------------
// GRU scan: one CTA per (b,e) lane, 384 threads (one per gate row).
// ---------------------------------------------------------------------------
__global__ __launch_bounds__(384) void gru_k(
    const float* __restrict__ gp, const float* __restrict__ rw,
    const float* __restrict__ Whh, const float* __restrict__ b_ih,
    const float* __restrict__ b_hh, const float* __restrict__ state0,
    float* __restrict__ state_out)
{
    extern __shared__ float sm[];
    float4* swW = (float4*)sm;              // 12288 float4 (196608 B)
    float* h_s  = sm + 49152;               // 128
    float* sA   = h_s + 128;                // 384
    float* sHn  = sA + 384;                 // 128

    int tid = threadIdx.x;
    int L = blockIdx.x;
    int b = L >> 3, e = L & 7;

    const float4* Whh4 = (const float4*)Whh;
    for (int idx = tid; idx < 12288; idx += 384) {
        int o = idx >> 5, j = idx & 31;
        swW[(o << 5) | (j ^ (o & 7))] = Whh4[idx];
    }
    if (tid < 128) h_s[tid] = state0[(e << 7) + tid];
    float bihr = b_ih[tid];
    float bhhr = b_hh[tid];
    int base = tid << 5, sw = tid & 7;
    size_t gpBase = ((size_t)b * Tc) * 384 + tid;
    size_t rwBase = ((size_t)b * Tc) * 8 + e;
    size_t soBase = (((size_t)b * Tc) * 8 + e) * 128;
    __syncthreads();

    const float4* h4 = (const float4*)h_s;
    float gpc = gp[gpBase];
    float rwc = rw[rwBase];

    for (int t = 0; t < Tc; ++t) {
        float gpn = 0.f, rwn = 0.f;
        if (t + 1 < Tc) {
            gpn = gp[gpBase + (size_t)(t + 1) * 384];
            rwn = rw[rwBase + (size_t)(t + 1) * 8];
        }
        float acc = bhhr;
#pragma unroll
        for (int j = 0; j < 32; ++j) {
            float4 w = swW[base + (j ^ sw)];
            float4 hv = h4[j];
            acc = fmaf(w.x, hv.x, acc);
            acc = fmaf(w.y, hv.y, acc);
            acc = fmaf(w.z, hv.z, acc);
            acc = fmaf(w.w, hv.w, acc);
        }
        float gi = fmaf(rwc, gpc, bihr);
        if (tid < 256) sA[tid] = gi + acc;
        else { sA[tid] = gi; sHn[tid - 256] = acc; }
        __syncthreads();
        if (tid < 128) {
            float r = 1.f / (1.f + expf(-sA[tid]));
            float z = 1.f / (1.f + expf(-sA[128 + tid]));
            float n = tanhf(fmaf(r, sHn[tid], sA[256 + tid]));
            float hold = h_s[tid];
            float hn = fmaf(z, hold - n, n);
            h_s[tid] = hn;
            state_out[soBase + (size_t)t * 1024 + tid] = hn;
        }
        __syncthreads();
        gpc = gpn; rwc = rwn;
    }
}

// ---------------------------------------------------------------------------
// Head layer 2: GELU(exact) + 64->1 dot, one warp per (row, head)
// ---------------------------------------------------------------------------
__global__ __launch_bounds__(256) void heads_l2_k(
    const float* __restrict__ hdn,
    const float* __restrict__ Wh2, const float* __restrict__ bh2,
    const float* __restrict__ Wt2, const float* __restrict__ bt2,
    const float* __restrict__ Wv2, const float* __restrict__ bv2,
    float* __restrict__ oh, float* __restrict__ ot, float* __restrict__ ov)
{
    int task = blockIdx.x * 8 + (threadIdx.x >> 5);
    int lane = threadIdx.x & 31;
    int row = task / 3, h = task - row * 3;
    const float* W2 = (h == 0) ? Wh2 : (h == 1 ? Wt2 : Wv2);
    const float* b2 = (h == 0) ? bh2 : (h == 1 ? bt2 : bv2);
    const float* x = hdn + (size_t)row * 192 + h * 64;
    float x1 = x[lane], x2 = x[lane + 32];
    float g1 = 0.5f * x1 * (1.f + erff(x1 * 0.7071067811865476f));
    float g2 = 0.5f * x2 * (1.f + erff(x2 * 0.7071067811865476f));
    float acc = g1 * W2[lane] + g2 * W2[lane + 32];
#pragma unroll
    for (int s = 16; s; s >>= 1) acc += __shfl_xor_sync(0xffffffffu, acc, s);
    if (lane == 0) {
        float* o = (h == 0) ? oh : (h == 1 ? ot : ov);
        o[row] = acc + b2[0];
    }
}

// ---------------------------------------------------------------------------
// Launch
// ---------------------------------------------------------------------------
extern "C" void kernel_launch(void* const* d_in, const int* in_sizes, int n_in,
                              void* d_out, int out_size)
{
    const float* h_seq = (const float*)d_in[0];
    const float* keys  = (const float*)d_in[1];
    const float* state0= (const float*)d_in[2];
    const float* Wi    = (const float*)d_in[3];
    const float* bi    = (const float*)d_in[4];
    const float* W_ih  = (const float*)d_in[5];
    const float* W_hh  = (const float*)d_in[6];
    const float* b_ih  = (const float*)d_in[7];
    const float* b_hh  = (const float*)d_in[8];
    const float* Wm    = (const float*)d_in[9];
    const float* bm    = (const float*)d_in[10];
    const float* Ws    = (const float*)d_in[11];
    const float* bs    = (const float*)d_in[12];
    const float* Wh1   = (const float*)d_in[13];
    const float* bh1   = (const float*)d_in[14];
    const float* Wh2   = (const float*)d_in[15];
    const float* bh2   = (const float*)d_in[16];
    const float* Wt1   = (const float*)d_in[17];
    const float* bt1   = (const float*)d_in[18];
    const float* Wt2   = (const float*)d_in[19];
    const float* bt2   = (const float*)d_in[20];
    const float* Wv1   = (const float*)d_in[21];
    const float* bv1   = (const float*)d_in[22];
    const float* Wv2   = (const float*)d_in[23];
    const float* bv2   = (const float*)d_in[24];

    float* out = (float*)d_out;
    float* o_pooled = out;                                     // [8,1024,768]
    float* o_mem    = o_pooled + (size_t)8192 * 768;           // [8,1024,8,768]
    float* o_state  = o_mem + (size_t)65536 * 768;             // [8,1024,8,128]
    float* o_holder = o_state + (size_t)65536 * 128;           // [8,1024,8]
    float* o_tagged = o_holder + 65536;
    float* o_visib  = o_tagged + 65536;
    float* o_route  = o_visib + 65536;

    float *p_Wit, *p_Wiht, *p_Wmt, *p_Wst, *p_Whr, *p_bhcat;
    float *p_proj, *p_gp, *p_Cp, *p_Cpt, *p_bpool, *p_hdn;
    cudaGetSymbolAddress((void**)&p_Wit,   g_Wit);
    cudaGetSymbolAddress((void**)&p_Wiht,  g_Wiht);
    cudaGetSymbolAddress((void**)&p_Wmt,   g_Wmt);
    cudaGetSymbolAddress((void**)&p_Wst,   g_Wst);
    cudaGetSymbolAddress((void**)&p_Whr,   g_Whr);
    cudaGetSymbolAddress((void**)&p_bhcat, g_bhcat);
    cudaGetSymbolAddress((void**)&p_proj,  g_proj);
    cudaGetSymbolAddress((void**)&p_gp,    g_gp);
    cudaGetSymbolAddress((void**)&p_Cp,    g_Cp);
    cudaGetSymbolAddress((void**)&p_Cpt,   g_Cpt);
    cudaGetSymbolAddress((void**)&p_bpool, g_bpool);
    cudaGetSymbolAddress((void**)&p_hdn,   g_hdn);

    dim3 tb(32, 8);
    // Weight prep
    transpose_k<<<dim3(24, 4),  tb>>>(Wi,   p_Wit,  128, 768);
    transpose_k<<<dim3(4, 12),  tb>>>(W_ih, p_Wiht, 384, 128);
    transpose_k<<<dim3(4, 24),  tb>>>(Wm,   p_Wmt,  768, 128);
    transpose_k<<<dim3(192, 24), tb>>>(Ws,  p_Wst,  768, 6144);
    headscat_k<<<96, 256>>>(Wh1, Wt1, Wv1, bh1, bt1, bv1, p_Whr, p_bhcat);

    // Routing (writes route_weights output, consumed by GRU)
    route_k<<<1024, 256>>>(h_seq, keys, o_route);

    // fp32 front GEMMs (keep state path fp32-accurate)
    sgemm_k<<<dim3(2, 128), 256>>>(h_seq, p_Wit, bi, p_proj, 8192, 128, 768, 0, 0, 0);
    sgemm_k<<<dim3(6, 128), 256>>>(p_proj, p_Wiht, nullptr, p_gp, 8192, 384, 128, 0, 0, 0);
    // Cp[e] = Wm^T @ Ws_e^T  -> g_Cp [1024,768], then transpose -> [768,1024]
    sgemm_k<<<dim3(12, 2, 8), 256>>>(p_Wmt, p_Wst, nullptr, p_Cp,
                                     128, 768, 768, 0, 589824, 98304);
    transpose_k<<<dim3(24, 32), tb>>>(p_Cp, p_Cpt, 1024, 768);
    bpool_k<<<768, 256>>>(Ws, bm, bs, p_bpool);

    // GRU scan (sequential over T) -> state_stack output
    cudaFuncSetAttribute(gru_k, cudaFuncAttributeMaxDynamicSharedMemorySize, 199168);
    gru_k<<<64, 384, 199168>>>(p_gp, o_route, W_hh, b_ih, b_hh, state0, o_state);

    // Tail GEMMs on tensor cores (tf32)
    const int tfsmem = 2 * TF_STAGE * 4;  // 55296 bytes
    cudaFuncSetAttribute(gemm_tf32_k, cudaFuncAttributeMaxDynamicSharedMemorySize, tfsmem);

    // memory_stack = state @ Wm^T + bm   [65536,768]
    gemm_tf32_k<<<dim3(12, 512), 256, tfsmem>>>(o_state, Wm, bm, o_mem,
                                                65536, 768, 128, 128, 768, 0, 0);
    // heads layer-1 (3 heads fused)      [65536,192]
    gemm_tf32_k<<<dim3(3, 512), 256, tfsmem>>>(o_state, p_Whr, p_bhcat, p_hdn,
                                               65536, 192, 128, 128, 192, 0, 0);
    heads_l2_k<<<24576, 256>>>(p_hdn, Wh2, bh2, Wt2, bt2, Wv2, bv2,
                               o_holder, o_tagged, o_visib);
    // pooled = state.reshape(8192,1024) @ Cpt^T + bpool   [8192,768]
    gemm_tf32_k<<<dim3(12, 64), 256, tfsmem>>>(o_state, p_Cpt, p_bpool, o_pooled,
                                               8192, 768, 1024, 1024, 768, 0, 0);
}

// round 4
// speedup vs baseline: 1.9610x; 1.6500x over previous
#include <cuda_runtime.h>
#include <math.h>

// Problem constants
#define Bc  8
#define Tc  1024
#define Dc  768
#define NEc 8
#define DSc 128
#define Hc  64

// ---------------------------------------------------------------------------
// Scratch (static __device__ arrays — no allocation at runtime)
// ---------------------------------------------------------------------------
__device__ float g_Wit[768 * 128];      // Wi^T            [768,128]
__device__ float g_Wiht[128 * 384];     // W_ih^T          [128,384]
__device__ float g_Wmt[128 * 768];      // Wm^T            [128,768]
__device__ float g_Wst[6144 * 768];     // Ws^T            [6144,768]
__device__ float g_Whr[192 * 128];      // [Wh1;Wt1;Wv1] row-concat [192,128]
__device__ float g_bhcat[192];
__device__ float g_proj[8192 * 128];    // h_seq @ Wi^T + bi
__device__ float g_gp[8192 * 384];      // proj @ W_ih^T (no bias)
__device__ float g_Cp[1024 * 768];      // combined pooled weight [NE*DS, D]
__device__ float g_Cpt[768 * 1024];     // Cp^T  [D, NE*DS]
__device__ float g_bpool[768];          // combined pooled bias
__device__ float g_hdn[65536 * 192];    // head layer-1 pre-GELU

// ---------------------------------------------------------------------------
// Packed fp32x2 FMA (sm_100+): two independent fp32 FMAs per instruction.
// Bit-exact vs two fmaf's.
// ---------------------------------------------------------------------------
__device__ __forceinline__ unsigned long long ffma2(
    unsigned long long a, unsigned long long b, unsigned long long c)
{
    unsigned long long d;
    asm("fma.rn.f32x2 %0, %1, %2, %3;" : "=l"(d) : "l"(a), "l"(b), "l"(c));
    return d;
}
__device__ __forceinline__ unsigned long long pack2(float lo, float hi)
{
    unsigned long long d;
    asm("mov.b64 %0, {%1, %2};" : "=l"(d) : "f"(lo), "f"(hi));
    return d;
}
__device__ __forceinline__ float lo2(unsigned long long v)
{ return __uint_as_float((unsigned)(v & 0xffffffffull)); }
__device__ __forceinline__ float hi2(unsigned long long v)
{ return __uint_as_float((unsigned)(v >> 32)); }

// ---------------------------------------------------------------------------
// Generic transpose: out[C,R] = in[R,C]^T
// ---------------------------------------------------------------------------
__global__ void transpose_k(const float* __restrict__ in, float* __restrict__ out,
                            int R, int C)
{
    __shared__ float t[32][33];
    int c0 = blockIdx.x * 32, r0 = blockIdx.y * 32;
#pragma unroll
    for (int i = 0; i < 4; i++) {
        int r = r0 + threadIdx.y + i * 8;
        int c = c0 + threadIdx.x;
        if (r < R && c < C) t[threadIdx.y + i * 8][threadIdx.x] = in[(size_t)r * C + c];
    }
    __syncthreads();
#pragma unroll
    for (int i = 0; i < 4; i++) {
        int c = c0 + threadIdx.y + i * 8;
        int r = r0 + threadIdx.x;
        if (r < R && c < C) out[(size_t)c * R + r] = t[threadIdx.x][threadIdx.y + i * 8];
    }
}

// ---------------------------------------------------------------------------
// Row-concat head layer-1 weights [192,128] and biases [192]
// ---------------------------------------------------------------------------
__global__ void headscat_k(const float* __restrict__ Wh1, const float* __restrict__ Wt1,
                           const float* __restrict__ Wv1, const float* __restrict__ bh1,
                           const float* __restrict__ bt1, const float* __restrict__ bv1,
                           float* __restrict__ Wr, float* __restrict__ bcat)
{
    int idx = blockIdx.x * 256 + threadIdx.x;
    if (idx < 24576) {
        const float* src = (idx < 8192) ? Wh1 : (idx < 16384 ? Wt1 : Wv1);
        Wr[idx] = src[idx & 8191];
    }
    if (idx < 192) {
        int h = idx >> 6, n = idx & 63;
        const float* bb = (h == 0) ? bh1 : (h == 1 ? bt1 : bv1);
        bcat[idx] = bb[n];
    }
}

// ---------------------------------------------------------------------------
// Routing: logits + softmax over NE=8.  One warp per (b,t) row.
// ---------------------------------------------------------------------------
__global__ __launch_bounds__(256) void route_k(const float* __restrict__ h_seq,
                                               const float* __restrict__ keys,
                                               float* __restrict__ rw)
{
    __shared__ float4 ks[8 * 192];  // 8 keys x 768 floats
    int tid = threadIdx.x;
    const float4* k4 = (const float4*)keys;
    for (int i = tid; i < 1536; i += 256) ks[i] = k4[i];
    __syncthreads();

    int r = blockIdx.x * 8 + (tid >> 5);
    int lane = tid & 31;
    const float4* h4 = (const float4*)h_seq + (size_t)r * 192;
    float acc[8];
#pragma unroll
    for (int e = 0; e < 8; e++) acc[e] = 0.f;
#pragma unroll
    for (int i = 0; i < 6; i++) {
        float4 hv = h4[i * 32 + lane];
#pragma unroll
        for (int e = 0; e < 8; e++) {
            float4 kv = ks[e * 192 + i * 32 + lane];
            acc[e] += hv.x * kv.x + hv.y * kv.y + hv.z * kv.z + hv.w * kv.w;
        }
    }
#pragma unroll
    for (int e = 0; e < 8; e++)
#pragma unroll
        for (int s = 16; s; s >>= 1) acc[e] += __shfl_xor_sync(0xffffffffu, acc[e], s);

    if (lane == 0) {
        const float inv = 1.0f / 27.712812921102035f;  // 1/(sqrt(768)*1.0)
        float m = -1e30f;
#pragma unroll
        for (int e = 0; e < 8; e++) { acc[e] *= inv; m = fmaxf(m, acc[e]); }
        float s = 0.f;
#pragma unroll
        for (int e = 0; e < 8; e++) { acc[e] = expf(acc[e] - m); s += acc[e]; }
        float is = 1.f / s;
#pragma unroll
        for (int e = 0; e < 8; e++) rw[(size_t)r * 8 + e] = acc[e] * is;
    }
}

// ---------------------------------------------------------------------------
// Combined pooled bias: bpool[d] = bs[d] + sum_{e,j} bm[j] * Ws[d, e*768+j]
// ---------------------------------------------------------------------------
__global__ void bpool_k(const float* __restrict__ Ws, const float* __restrict__ bm,
                        const float* __restrict__ bs, float* __restrict__ bp)
{
    __shared__ float red[256];
    int d = blockIdx.x;
    const float* row = Ws + (size_t)d * 6144;
    float acc = 0.f;
    for (int e = 0; e < 8; e++)
        for (int j = threadIdx.x; j < 768; j += 256)
            acc += row[e * 768 + j] * bm[j];
    red[threadIdx.x] = acc;
    __syncthreads();
    for (int s = 128; s; s >>= 1) {
        if (threadIdx.x < s) red[threadIdx.x] += red[threadIdx.x + s];
        __syncthreads();
    }
    if (threadIdx.x == 0) bp[d] = bs[d] + red[0];
}

// ---------------------------------------------------------------------------
// fp32 SGEMM with packed f32x2 FMAs: C[M,N] = A[M,K] @ B[K,N] (+ bias[N]).
// 64x64x16 tiles.  Bit-exact fp32.
// ---------------------------------------------------------------------------
__global__ __launch_bounds__(256) void sgemm_k(
    const float* __restrict__ A, const float* __restrict__ B,
    const float* __restrict__ bias, float* __restrict__ C,
    int M, int N, int K, long long aBS, long long bBS, long long cBS)
{
    A += (size_t)blockIdx.z * aBS;
    B += (size_t)blockIdx.z * bBS;
    C += (size_t)blockIdx.z * cBS;

    __shared__ float As[16][68];
    __shared__ __align__(16) float Bs[16][64];
    int tid = threadIdx.x;
    int m0 = blockIdx.y * 64, n0 = blockIdx.x * 64;
    int ar = tid >> 2, ac = (tid & 3) << 2;
    int br = tid >> 4, bc = (tid & 15) << 2;
    int tx = tid & 15, ty = tid >> 4;

    unsigned long long acc2[4][2];
#pragma unroll
    for (int i = 0; i < 4; i++) { acc2[i][0] = 0ull; acc2[i][1] = 0ull; }

    const float* Ap = A + (size_t)(m0 + ar) * K + ac;
    const float* Bp = B + (size_t)br * N + n0 + bc;
    int nk = K >> 4;
    float4 a4 = *(const float4*)Ap;
    float4 b4 = *(const float4*)Bp;

    for (int kt = 0; kt < nk; ++kt) {
        As[ac + 0][ar] = a4.x; As[ac + 1][ar] = a4.y;
        As[ac + 2][ar] = a4.z; As[ac + 3][ar] = a4.w;
        *(float4*)&Bs[br][bc] = b4;
        __syncthreads();
        if (kt + 1 < nk) {
            a4 = *(const float4*)(Ap + (kt + 1) * 16);
            b4 = *(const float4*)(Bp + (size_t)(kt + 1) * 16 * N);
        }
#pragma unroll
        for (int k = 0; k < 16; ++k) {
            float4 av = *(const float4*)&As[k][ty << 2];
            ulonglong2 bv = *(const ulonglong2*)&Bs[k][tx << 2];
            unsigned long long a0 = pack2(av.x, av.x);
            unsigned long long a1 = pack2(av.y, av.y);
            unsigned long long a2 = pack2(av.z, av.z);
            unsigned long long a3 = pack2(av.w, av.w);
            acc2[0][0] = ffma2(a0, bv.x, acc2[0][0]);
            acc2[0][1] = ffma2(a0, bv.y, acc2[0][1]);
            acc2[1][0] = ffma2(a1, bv.x, acc2[1][0]);
            acc2[1][1] = ffma2(a1, bv.y, acc2[1][1]);
            acc2[2][0] = ffma2(a2, bv.x, acc2[2][0]);
            acc2[2][1] = ffma2(a2, bv.y, acc2[2][1]);
            acc2[3][0] = ffma2(a3, bv.x, acc2[3][0]);
            acc2[3][1] = ffma2(a3, bv.y, acc2[3][1]);
        }
        __syncthreads();
    }

    float4 bb = make_float4(0.f, 0.f, 0.f, 0.f);
    if (bias) bb = *(const float4*)&bias[n0 + (tx << 2)];
#pragma unroll
    for (int i = 0; i < 4; i++) {
        float4 o;
        o.x = lo2(acc2[i][0]) + bb.x; o.y = hi2(acc2[i][0]) + bb.y;
        o.z = lo2(acc2[i][1]) + bb.z; o.w = hi2(acc2[i][1]) + bb.w;
        *(float4*)&C[(size_t)(m0 + (ty << 2) + i) * N + n0 + (tx << 2)] = o;
    }
}

// ---------------------------------------------------------------------------
// TF32 tensor-core GEMM (unchanged from R3): C = A @ W^T (+bias)
// ---------------------------------------------------------------------------
__device__ __forceinline__ float4 cvt_tf32_4(float4 v)
{
    float4 r;
    asm("cvt.rna.tf32.f32 %0, %1;" : "=f"(r.x) : "f"(v.x));
    asm("cvt.rna.tf32.f32 %0, %1;" : "=f"(r.y) : "f"(v.y));
    asm("cvt.rna.tf32.f32 %0, %1;" : "=f"(r.z) : "f"(v.z));
    asm("cvt.rna.tf32.f32 %0, %1;" : "=f"(r.w) : "f"(v.w));
    return r;
}

__device__ __forceinline__ void mma_tf32(float* c, const unsigned* a, const unsigned* b)
{
    asm volatile(
        "mma.sync.aligned.m16n8k8.row.col.f32.tf32.tf32.f32 "
        "{%0,%1,%2,%3}, {%4,%5,%6,%7}, {%8,%9}, {%0,%1,%2,%3};"
        : "+f"(c[0]), "+f"(c[1]), "+f"(c[2]), "+f"(c[3])
        : "r"(a[0]), "r"(a[1]), "r"(a[2]), "r"(a[3]), "r"(b[0]), "r"(b[1]));
}

#define TFPAD 36
#define TF_STAGE (128 * TFPAD + 64 * TFPAD)   // 6912 floats per stage

__global__ __launch_bounds__(256) void gemm_tf32_k(
    const float* __restrict__ A, const float* __restrict__ W,
    const float* __restrict__ bias, float* __restrict__ C,
    int M, int N, int K, int lda, int ldc,
    long long aOff, long long cOff)
{
    extern __shared__ float sm[];
    A += (size_t)blockIdx.z * aOff;
    C += (size_t)blockIdx.z * cOff;

    const int tid = threadIdx.x;
    const int wid = tid >> 5, lane = tid & 31;
    const int g = lane >> 2, tg = lane & 3;
    const int mB = (wid & 3) << 5, nB = (wid >> 2) << 5;
    const int m0 = blockIdx.y << 7, n0 = blockIdx.x << 6;

    const int arow = tid >> 3, acol = (tid & 7) << 2;
    const float* Ag = A + (size_t)(m0 + arow) * lda + acol;
    const float* Wg = W + (size_t)(n0 + arow) * K + acol;

    float acc[2][4][4];
#pragma unroll
    for (int i = 0; i < 2; i++)
#pragma unroll
        for (int j = 0; j < 4; j++)
#pragma unroll
            for (int l = 0; l < 4; l++) acc[i][j][l] = 0.f;

    float4 aR[4], wR[2];
#pragma unroll
    for (int i = 0; i < 4; i++) aR[i] = *(const float4*)(Ag + (size_t)i * 32 * lda);
#pragma unroll
    for (int i = 0; i < 2; i++) wR[i] = *(const float4*)(Wg + (size_t)i * 32 * K);

    {
        float* As = sm;
        float* Bs = sm + 128 * TFPAD;
#pragma unroll
        for (int i = 0; i < 4; i++)
            *(float4*)&As[(arow + i * 32) * TFPAD + acol] = cvt_tf32_4(aR[i]);
#pragma unroll
        for (int i = 0; i < 2; i++)
            *(float4*)&Bs[(arow + i * 32) * TFPAD + acol] = cvt_tf32_4(wR[i]);
    }
    __syncthreads();

    const int nk = K >> 5;
    for (int kc = 0; kc < nk; ++kc) {
        if (kc + 1 < nk) {
            const float* Ag2 = Ag + (kc + 1) * 32;
            const float* Wg2 = Wg + (kc + 1) * 32;
#pragma unroll
            for (int i = 0; i < 4; i++) aR[i] = *(const float4*)(Ag2 + (size_t)i * 32 * lda);
#pragma unroll
            for (int i = 0; i < 2; i++) wR[i] = *(const float4*)(Wg2 + (size_t)i * 32 * K);
        }

        const float* As = sm + (kc & 1) * TF_STAGE;
        const float* Bs = As + 128 * TFPAD;
#pragma unroll
        for (int kf = 0; kf < 4; ++kf) {
            const int kk = (kf << 3) + tg;
            unsigned a[2][4], b[4][2];
#pragma unroll
            for (int mf = 0; mf < 2; ++mf) {
                int r = mB + (mf << 4) + g;
                a[mf][0] = __float_as_uint(As[r * TFPAD + kk]);
                a[mf][1] = __float_as_uint(As[(r + 8) * TFPAD + kk]);
                a[mf][2] = __float_as_uint(As[r * TFPAD + kk + 4]);
                a[mf][3] = __float_as_uint(As[(r + 8) * TFPAD + kk + 4]);
            }
#pragma unroll
            for (int nf = 0; nf < 4; ++nf) {
                int n = nB + (nf << 3) + g;
                b[nf][0] = __float_as_uint(Bs[n * TFPAD + kk]);
                b[nf][1] = __float_as_uint(Bs[n * TFPAD + kk + 4]);
            }
#pragma unroll
            for (int mf = 0; mf < 2; ++mf)
#pragma unroll
                for (int nf = 0; nf < 4; ++nf)
                    mma_tf32(acc[mf][nf], a[mf], b[nf]);
        }

        if (kc + 1 < nk) {
            float* Ad = sm + ((kc + 1) & 1) * TF_STAGE;
            float* Bd = Ad + 128 * TFPAD;
#pragma unroll
            for (int i = 0; i < 4; i++)
                *(float4*)&Ad[(arow + i * 32) * TFPAD + acol] = cvt_tf32_4(aR[i]);
#pragma unroll
            for (int i = 0; i < 2; i++)
                *(float4*)&Bd[(arow + i * 32) * TFPAD + acol] = cvt_tf32_4(wR[i]);
            __syncthreads();
        }
    }

#pragma unroll
    for (int mf = 0; mf < 2; ++mf)
#pragma unroll
        for (int nf = 0; nf < 4; ++nf) {
            int row = m0 + mB + (mf << 4) + g;
            int col = n0 + nB + (nf << 3) + (tg << 1);
            float2 bb = make_float2(0.f, 0.f);
            if (bias) bb = *(const float2*)&bias[col];
            float2 v;
            v.x = acc[mf][nf][0] + bb.x;
            v.y = acc[mf][nf][1] + bb.y;
            *(float2*)&C[(size_t)row * ldc + col] = v;
            v.x = acc[mf][nf][2] + bb.x;
            v.y = acc[mf][nf][3] + bb.y;
            *(float2*)&C[(size_t)(row + 8) * ldc + col] = v;
        }
}

// ---------------------------------------------------------------------------
// GRU scan v2: one CTA per (b,e) lane, 384 threads (one per gate row).
// W_hh row lives in REGISTERS (128 floats/thread) — no per-step smem W
// traffic.  h broadcast from smem (free), dot via packed f32x2 FMAs.
// ---------------------------------------------------------------------------
__global__ __launch_bounds__(384) void gru_k(
    const float* __restrict__ gp, const float* __restrict__ rw,
    const float* __restrict__ Whh, const float* __restrict__ b_ih,
    const float* __restrict__ b_hh, const float* __restrict__ state0,
    float* __restrict__ state_out)
{
    __shared__ __align__(16) float h_s[128];
    __shared__ float sA[384];
    __shared__ float sHn[128];

    int tid = threadIdx.x;
    int L = blockIdx.x;
    int b = L >> 3, e = L & 7;

    // W_hh row of this gate -> registers (32 x ulonglong2 = 128 floats)
    ulonglong2 w[32];
    const ulonglong2* Wrow = (const ulonglong2*)(Whh + (size_t)tid * 128);
#pragma unroll
    for (int j = 0; j < 32; ++j) w[j] = Wrow[j];

    if (tid < 128) h_s[tid] = state0[(e << 7) + tid];
    float bihr = b_ih[tid];
    float bhhr = b_hh[tid];
    size_t gpBase = ((size_t)b * Tc) * 384 + tid;
    size_t rwBase = ((size_t)b * Tc) * 8 + e;
    size_t soBase = (((size_t)b * Tc) * 8 + e) * 128;
    __syncthreads();

    const ulonglong2* h2 = (const ulonglong2*)h_s;
    float gpc = gp[gpBase];
    float rwc = rw[rwBase];

    for (int t = 0; t < Tc; ++t) {
        float gpn = 0.f, rwn = 0.f;
        if (t + 1 < Tc) {
            gpn = gp[gpBase + (size_t)(t + 1) * 384];
            rwn = rw[rwBase + (size_t)(t + 1) * 8];
        }
        unsigned long long acc0 = 0ull, acc1 = 0ull;
#pragma unroll
        for (int j = 0; j < 32; ++j) {
            ulonglong2 hv = h2[j];             // warp-uniform broadcast
            acc0 = ffma2(w[j].x, hv.x, acc0);
            acc1 = ffma2(w[j].y, hv.y, acc1);
        }
        float acc = lo2(acc0) + hi2(acc0) + lo2(acc1) + hi2(acc1) + bhhr;
        float gi = fmaf(rwc, gpc, bihr);
        if (tid < 256) sA[tid] = gi + acc;
        else { sA[tid] = gi; sHn[tid - 256] = acc; }
        __syncthreads();
        if (tid < 128) {
            float r = 1.f / (1.f + expf(-sA[tid]));
            float z = 1.f / (1.f + expf(-sA[128 + tid]));
            float n = tanhf(fmaf(r, sHn[tid], sA[256 + tid]));
            float hold = h_s[tid];
            float hn = fmaf(z, hold - n, n);
            h_s[tid] = hn;
            state_out[soBase + (size_t)t * 1024 + tid] = hn;
        }
        __syncthreads();
        gpc = gpn; rwc = rwn;
    }
}

// ---------------------------------------------------------------------------
// Head layer 2: GELU(exact) + 64->1 dot, one warp per (row, head)
// ---------------------------------------------------------------------------
__global__ __launch_bounds__(256) void heads_l2_k(
    const float* __restrict__ hdn,
    const float* __restrict__ Wh2, const float* __restrict__ bh2,
    const float* __restrict__ Wt2, const float* __restrict__ bt2,
    const float* __restrict__ Wv2, const float* __restrict__ bv2,
    float* __restrict__ oh, float* __restrict__ ot, float* __restrict__ ov)
{
    int task = blockIdx.x * 8 + (threadIdx.x >> 5);
    int lane = threadIdx.x & 31;
    int row = task / 3, h = task - row * 3;
    const float* W2 = (h == 0) ? Wh2 : (h == 1 ? Wt2 : Wv2);
    const float* b2 = (h == 0) ? bh2 : (h == 1 ? bt2 : bv2);
    const float* x = hdn + (size_t)row * 192 + h * 64;
    float x1 = x[lane], x2 = x[lane + 32];
    float g1 = 0.5f * x1 * (1.f + erff(x1 * 0.7071067811865476f));
    float g2 = 0.5f * x2 * (1.f + erff(x2 * 0.7071067811865476f));
    float acc = g1 * W2[lane] + g2 * W2[lane + 32];
#pragma unroll
    for (int s = 16; s; s >>= 1) acc += __shfl_xor_sync(0xffffffffu, acc, s);
    if (lane == 0) {
        float* o = (h == 0) ? oh : (h == 1 ? ot : ov);
        o[row] = acc + b2[0];
    }
}

// ---------------------------------------------------------------------------
// Launch
// ---------------------------------------------------------------------------
extern "C" void kernel_launch(void* const* d_in, const int* in_sizes, int n_in,
                              void* d_out, int out_size)
{
    const float* h_seq = (const float*)d_in[0];
    const float* keys  = (const float*)d_in[1];
    const float* state0= (const float*)d_in[2];
    const float* Wi    = (const float*)d_in[3];
    const float* bi    = (const float*)d_in[4];
    const float* W_ih  = (const float*)d_in[5];
    const float* W_hh  = (const float*)d_in[6];
    const float* b_ih  = (const float*)d_in[7];
    const float* b_hh  = (const float*)d_in[8];
    const float* Wm    = (const float*)d_in[9];
    const float* bm    = (const float*)d_in[10];
    const float* Ws    = (const float*)d_in[11];
    const float* bs    = (const float*)d_in[12];
    const float* Wh1   = (const float*)d_in[13];
    const float* bh1   = (const float*)d_in[14];
    const float* Wh2   = (const float*)d_in[15];
    const float* bh2   = (const float*)d_in[16];
    const float* Wt1   = (const float*)d_in[17];
    const float* bt1   = (const float*)d_in[18];
    const float* Wt2   = (const float*)d_in[19];
    const float* bt2   = (const float*)d_in[20];
    const float* Wv1   = (const float*)d_in[21];
    const float* bv1   = (const float*)d_in[22];
    const float* Wv2   = (const float*)d_in[23];
    const float* bv2   = (const float*)d_in[24];

    float* out = (float*)d_out;
    float* o_pooled = out;                                     // [8,1024,768]
    float* o_mem    = o_pooled + (size_t)8192 * 768;           // [8,1024,8,768]
    float* o_state  = o_mem + (size_t)65536 * 768;             // [8,1024,8,128]
    float* o_holder = o_state + (size_t)65536 * 128;           // [8,1024,8]
    float* o_tagged = o_holder + 65536;
    float* o_visib  = o_tagged + 65536;
    float* o_route  = o_visib + 65536;

    float *p_Wit, *p_Wiht, *p_Wmt, *p_Wst, *p_Whr, *p_bhcat;
    float *p_proj, *p_gp, *p_Cp, *p_Cpt, *p_bpool, *p_hdn;
    cudaGetSymbolAddress((void**)&p_Wit,   g_Wit);
    cudaGetSymbolAddress((void**)&p_Wiht,  g_Wiht);
    cudaGetSymbolAddress((void**)&p_Wmt,   g_Wmt);
    cudaGetSymbolAddress((void**)&p_Wst,   g_Wst);
    cudaGetSymbolAddress((void**)&p_Whr,   g_Whr);
    cudaGetSymbolAddress((void**)&p_bhcat, g_bhcat);
    cudaGetSymbolAddress((void**)&p_proj,  g_proj);
    cudaGetSymbolAddress((void**)&p_gp,    g_gp);
    cudaGetSymbolAddress((void**)&p_Cp,    g_Cp);
    cudaGetSymbolAddress((void**)&p_Cpt,   g_Cpt);
    cudaGetSymbolAddress((void**)&p_bpool, g_bpool);
    cudaGetSymbolAddress((void**)&p_hdn,   g_hdn);

    dim3 tb(32, 8);
    // Weight prep
    transpose_k<<<dim3(24, 4),  tb>>>(Wi,   p_Wit,  128, 768);
    transpose_k<<<dim3(4, 12),  tb>>>(W_ih, p_Wiht, 384, 128);
    transpose_k<<<dim3(4, 24),  tb>>>(Wm,   p_Wmt,  768, 128);
    transpose_k<<<dim3(192, 24), tb>>>(Ws,  p_Wst,  768, 6144);
    headscat_k<<<96, 256>>>(Wh1, Wt1, Wv1, bh1, bt1, bv1, p_Whr, p_bhcat);

    // Routing (writes route_weights output, consumed by GRU)
    route_k<<<1024, 256>>>(h_seq, keys, o_route);

    // fp32 front GEMMs (keep state path fp32-accurate)
    sgemm_k<<<dim3(2, 128), 256>>>(h_seq, p_Wit, bi, p_proj, 8192, 128, 768, 0, 0, 0);
    sgemm_k<<<dim3(6, 128), 256>>>(p_proj, p_Wiht, nullptr, p_gp, 8192, 384, 128, 0, 0, 0);
    // Cp[e] = Wm^T @ Ws_e^T  -> g_Cp [1024,768], then transpose -> [768,1024]
    sgemm_k<<<dim3(12, 2, 8), 256>>>(p_Wmt, p_Wst, nullptr, p_Cp,
                                     128, 768, 768, 0, 589824, 98304);
    transpose_k<<<dim3(24, 32), tb>>>(p_Cp, p_Cpt, 1024, 768);
    bpool_k<<<768, 256>>>(Ws, bm, bs, p_bpool);

    // GRU scan (sequential over T) -> state_stack output
    gru_k<<<64, 384>>>(p_gp, o_route, W_hh, b_ih, b_hh, state0, o_state);

    // Tail GEMMs on tensor cores (tf32)
    const int tfsmem = 2 * TF_STAGE * 4;  // 55296 bytes
    cudaFuncSetAttribute(gemm_tf32_k, cudaFuncAttributeMaxDynamicSharedMemorySize, tfsmem);

    // memory_stack = state @ Wm^T + bm   [65536,768]
    gemm_tf32_k<<<dim3(12, 512), 256, tfsmem>>>(o_state, Wm, bm, o_mem,
                                                65536, 768, 128, 128, 768, 0, 0);
    // heads layer-1 (3 heads fused)      [65536,192]
    gemm_tf32_k<<<dim3(3, 512), 256, tfsmem>>>(o_state, p_Whr, p_bhcat, p_hdn,
                                               65536, 192, 128, 128, 192, 0, 0);
    heads_l2_k<<<24576, 256>>>(p_hdn, Wh2, bh2, Wt2, bt2, Wv2, bv2,
                               o_holder, o_tagged, o_visib);
    // pooled = state.reshape(8192,1024) @ Cpt^T + bpool   [8192,768]
    gemm_tf32_k<<<dim3(12, 64), 256, tfsmem>>>(o_state, p_Cpt, p_bpool, o_pooled,
                                               8192, 768, 1024, 1024, 768, 0, 0);
}

// round 5
// speedup vs baseline: 2.3472x; 1.1970x over previous
#include <cuda_runtime.h>
#include <math.h>

// Problem constants
#define Bc  8
#define Tc  1024
#define Dc  768
#define NEc 8
#define DSc 128
#define Hc  64

// ---------------------------------------------------------------------------
// Scratch (static __device__ arrays — no allocation at runtime)
// ---------------------------------------------------------------------------
__device__ float g_Wit[768 * 128];      // Wi^T            [768,128]
__device__ float g_Wiht[128 * 384];     // W_ih^T          [128,384]
__device__ float g_Wmt[128 * 768];      // Wm^T            [128,768]
__device__ float g_Wst[6144 * 768];     // Ws^T            [6144,768]
__device__ float g_Whr[192 * 128];      // [Wh1;Wt1;Wv1] row-concat [192,128]
__device__ float g_bhcat[192];
__device__ float g_proj[8192 * 128];    // h_seq @ Wi^T + bi
__device__ float g_gp[8192 * 384];      // proj @ W_ih^T (no bias)
__device__ float g_Cp[1024 * 768];      // combined pooled weight [NE*DS, D]
__device__ float g_Cpt[768 * 1024];     // Cp^T  [D, NE*DS]
__device__ float g_bpool[768];          // combined pooled bias

// ---------------------------------------------------------------------------
// Packed fp32x2 FMA (sm_100+): two independent fp32 FMAs per instruction.
// ---------------------------------------------------------------------------
__device__ __forceinline__ unsigned long long ffma2(
    unsigned long long a, unsigned long long b, unsigned long long c)
{
    unsigned long long d;
    asm("fma.rn.f32x2 %0, %1, %2, %3;" : "=l"(d) : "l"(a), "l"(b), "l"(c));
    return d;
}
__device__ __forceinline__ unsigned long long pack2(float lo, float hi)
{
    unsigned long long d;
    asm("mov.b64 %0, {%1, %2};" : "=l"(d) : "f"(lo), "f"(hi));
    return d;
}
__device__ __forceinline__ float lo2(unsigned long long v)
{ return __uint_as_float((unsigned)(v & 0xffffffffull)); }
__device__ __forceinline__ float hi2(unsigned long long v)
{ return __uint_as_float((unsigned)(v >> 32)); }

// MUFU-based activations (~1e-6 error; no tanh.approx — too coarse)
__device__ __forceinline__ float fast_sigmoid(float x)
{
    float e = __expf(-x);
    float r;
    asm("rcp.approx.f32 %0, %1;" : "=f"(r) : "f"(1.0f + e));
    return r;
}
__device__ __forceinline__ float fast_tanh(float x)
{
    float e = __expf(x + x);           // e^{2x}; inf/0 limits give +-1 exactly
    float r;
    asm("rcp.approx.f32 %0, %1;" : "=f"(r) : "f"(1.0f + e));
    return fmaf(-2.0f, r, 1.0f);
}

// ---------------------------------------------------------------------------
// Generic transpose: out[C,R] = in[R,C]^T
// ---------------------------------------------------------------------------
__global__ void transpose_k(const float* __restrict__ in, float* __restrict__ out,
                            int R, int C)
{
    __shared__ float t[32][33];
    int c0 = blockIdx.x * 32, r0 = blockIdx.y * 32;
#pragma unroll
    for (int i = 0; i < 4; i++) {
        int r = r0 + threadIdx.y + i * 8;
        int c = c0 + threadIdx.x;
        if (r < R && c < C) t[threadIdx.y + i * 8][threadIdx.x] = in[(size_t)r * C + c];
    }
    __syncthreads();
#pragma unroll
    for (int i = 0; i < 4; i++) {
        int c = c0 + threadIdx.y + i * 8;
        int r = r0 + threadIdx.x;
        if (r < R && c < C) out[(size_t)c * R + r] = t[threadIdx.x][threadIdx.y + i * 8];
    }
}

// ---------------------------------------------------------------------------
// Row-concat head layer-1 weights [192,128] and biases [192]
// ---------------------------------------------------------------------------
__global__ void headscat_k(const float* __restrict__ Wh1, const float* __restrict__ Wt1,
                           const float* __restrict__ Wv1, const float* __restrict__ bh1,
                           const float* __restrict__ bt1, const float* __restrict__ bv1,
                           float* __restrict__ Wr, float* __restrict__ bcat)
{
    int idx = blockIdx.x * 256 + threadIdx.x;
    if (idx < 24576) {
        const float* src = (idx < 8192) ? Wh1 : (idx < 16384 ? Wt1 : Wv1);
        Wr[idx] = src[idx & 8191];
    }
    if (idx < 192) {
        int h = idx >> 6, n = idx & 63;
        const float* bb = (h == 0) ? bh1 : (h == 1 ? bt1 : bv1);
        bcat[idx] = bb[n];
    }
}

// ---------------------------------------------------------------------------
// Routing: logits + softmax over NE=8.  One warp per (b,t) row.
// ---------------------------------------------------------------------------
__global__ __launch_bounds__(256) void route_k(const float* __restrict__ h_seq,
                                               const float* __restrict__ keys,
                                               float* __restrict__ rw)
{
    __shared__ float4 ks[8 * 192];  // 8 keys x 768 floats
    int tid = threadIdx.x;
    const float4* k4 = (const float4*)keys;
    for (int i = tid; i < 1536; i += 256) ks[i] = k4[i];
    __syncthreads();

    int r = blockIdx.x * 8 + (tid >> 5);
    int lane = tid & 31;
    const float4* h4 = (const float4*)h_seq + (size_t)r * 192;
    float acc[8];
#pragma unroll
    for (int e = 0; e < 8; e++) acc[e] = 0.f;
#pragma unroll
    for (int i = 0; i < 6; i++) {
        float4 hv = h4[i * 32 + lane];
#pragma unroll
        for (int e = 0; e < 8; e++) {
            float4 kv = ks[e * 192 + i * 32 + lane];
            acc[e] += hv.x * kv.x + hv.y * kv.y + hv.z * kv.z + hv.w * kv.w;
        }
    }
#pragma unroll
    for (int e = 0; e < 8; e++)
#pragma unroll
        for (int s = 16; s; s >>= 1) acc[e] += __shfl_xor_sync(0xffffffffu, acc[e], s);

    if (lane == 0) {
        const float inv = 1.0f / 27.712812921102035f;  // 1/(sqrt(768)*1.0)
        float m = -1e30f;
#pragma unroll
        for (int e = 0; e < 8; e++) { acc[e] *= inv; m = fmaxf(m, acc[e]); }
        float s = 0.f;
#pragma unroll
        for (int e = 0; e < 8; e++) { acc[e] = expf(acc[e] - m); s += acc[e]; }
        float is = 1.f / s;
#pragma unroll
        for (int e = 0; e < 8; e++) rw[(size_t)r * 8 + e] = acc[e] * is;
    }
}

// ---------------------------------------------------------------------------
// Combined pooled bias: bpool[d] = bs[d] + sum_{e,j} bm[j] * Ws[d, e*768+j]
// ---------------------------------------------------------------------------
__global__ void bpool_k(const float* __restrict__ Ws, const float* __restrict__ bm,
                        const float* __restrict__ bs, float* __restrict__ bp)
{
    __shared__ float red[256];
    int d = blockIdx.x;
    const float* row = Ws + (size_t)d * 6144;
    float acc = 0.f;
    for (int e = 0; e < 8; e++)
        for (int j = threadIdx.x; j < 768; j += 256)
            acc += row[e * 768 + j] * bm[j];
    red[threadIdx.x] = acc;
    __syncthreads();
    for (int s = 128; s; s >>= 1) {
        if (threadIdx.x < s) red[threadIdx.x] += red[threadIdx.x + s];
        __syncthreads();
    }
    if (threadIdx.x == 0) bp[d] = bs[d] + red[0];
}

// ---------------------------------------------------------------------------
// fp32 SGEMM with packed f32x2 FMAs (bit-exact fp32).
// ---------------------------------------------------------------------------
__global__ __launch_bounds__(256) void sgemm_k(
    const float* __restrict__ A, const float* __restrict__ B,
    const float* __restrict__ bias, float* __restrict__ C,
    int M, int N, int K, long long aBS, long long bBS, long long cBS)
{
    A += (size_t)blockIdx.z * aBS;
    B += (size_t)blockIdx.z * bBS;
    C += (size_t)blockIdx.z * cBS;

    __shared__ float As[16][68];
    __shared__ __align__(16) float Bs[16][64];
    int tid = threadIdx.x;
    int m0 = blockIdx.y * 64, n0 = blockIdx.x * 64;
    int ar = tid >> 2, ac = (tid & 3) << 2;
    int br = tid >> 4, bc = (tid & 15) << 2;
    int tx = tid & 15, ty = tid >> 4;

    unsigned long long acc2[4][2];
#pragma unroll
    for (int i = 0; i < 4; i++) { acc2[i][0] = 0ull; acc2[i][1] = 0ull; }

    const float* Ap = A + (size_t)(m0 + ar) * K + ac;
    const float* Bp = B + (size_t)br * N + n0 + bc;
    int nk = K >> 4;
    float4 a4 = *(const float4*)Ap;
    float4 b4 = *(const float4*)Bp;

    for (int kt = 0; kt < nk; ++kt) {
        As[ac + 0][ar] = a4.x; As[ac + 1][ar] = a4.y;
        As[ac + 2][ar] = a4.z; As[ac + 3][ar] = a4.w;
        *(float4*)&Bs[br][bc] = b4;
        __syncthreads();
        if (kt + 1 < nk) {
            a4 = *(const float4*)(Ap + (kt + 1) * 16);
            b4 = *(const float4*)(Bp + (size_t)(kt + 1) * 16 * N);
        }
#pragma unroll
        for (int k = 0; k < 16; ++k) {
            float4 av = *(const float4*)&As[k][ty << 2];
            ulonglong2 bv = *(const ulonglong2*)&Bs[k][tx << 2];
            unsigned long long a0 = pack2(av.x, av.x);
            unsigned long long a1 = pack2(av.y, av.y);
            unsigned long long a2 = pack2(av.z, av.z);
            unsigned long long a3 = pack2(av.w, av.w);
            acc2[0][0] = ffma2(a0, bv.x, acc2[0][0]);
            acc2[0][1] = ffma2(a0, bv.y, acc2[0][1]);
            acc2[1][0] = ffma2(a1, bv.x, acc2[1][0]);
            acc2[1][1] = ffma2(a1, bv.y, acc2[1][1]);
            acc2[2][0] = ffma2(a2, bv.x, acc2[2][0]);
            acc2[2][1] = ffma2(a2, bv.y, acc2[2][1]);
            acc2[3][0] = ffma2(a3, bv.x, acc2[3][0]);
            acc2[3][1] = ffma2(a3, bv.y, acc2[3][1]);
        }
        __syncthreads();
    }

    float4 bb = make_float4(0.f, 0.f, 0.f, 0.f);
    if (bias) bb = *(const float4*)&bias[n0 + (tx << 2)];
#pragma unroll
    for (int i = 0; i < 4; i++) {
        float4 o;
        o.x = lo2(acc2[i][0]) + bb.x; o.y = hi2(acc2[i][0]) + bb.y;
        o.z = lo2(acc2[i][1]) + bb.z; o.w = hi2(acc2[i][1]) + bb.w;
        *(float4*)&C[(size_t)(m0 + (ty << 2) + i) * N + n0 + (tx << 2)] = o;
    }
}

// ---------------------------------------------------------------------------
// TF32 tensor-core GEMM helpers
// ---------------------------------------------------------------------------
__device__ __forceinline__ float4 cvt_tf32_4(float4 v)
{
    float4 r;
    asm("cvt.rna.tf32.f32 %0, %1;" : "=f"(r.x) : "f"(v.x));
    asm("cvt.rna.tf32.f32 %0, %1;" : "=f"(r.y) : "f"(v.y));
    asm("cvt.rna.tf32.f32 %0, %1;" : "=f"(r.z) : "f"(v.z));
    asm("cvt.rna.tf32.f32 %0, %1;" : "=f"(r.w) : "f"(v.w));
    return r;
}

__device__ __forceinline__ void mma_tf32(float* c, const unsigned* a, const unsigned* b)
{
    asm volatile(
        "mma.sync.aligned.m16n8k8.row.col.f32.tf32.tf32.f32 "
        "{%0,%1,%2,%3}, {%4,%5,%6,%7}, {%8,%9}, {%0,%1,%2,%3};"
        : "+f"(c[0]), "+f"(c[1]), "+f"(c[2]), "+f"(c[3])
        : "r"(a[0]), "r"(a[1]), "r"(a[2]), "r"(a[3]), "r"(b[0]), "r"(b[1]));
}

#define TFPAD 36
#define TF_STAGE (128 * TFPAD + 64 * TFPAD)   // 6912 floats per stage

// Shared mainloop: computes acc[2][4][4] for a 128x64 C tile.
// (macro-free: duplicated in the two kernels below via this inline)
struct TFAcc { float a[2][4][4]; };

__device__ __forceinline__ void tf32_mainloop(
    const float* __restrict__ A, const float* __restrict__ W,
    int K, int lda, int m0, int n0, float* sm, TFAcc& R)
{
    const int tid = threadIdx.x;
    const int arow = tid >> 3, acol = (tid & 7) << 2;
    const float* Ag = A + (size_t)(m0 + arow) * lda + acol;
    const float* Wg = W + (size_t)(n0 + arow) * K + acol;

#pragma unroll
    for (int i = 0; i < 2; i++)
#pragma unroll
        for (int j = 0; j < 4; j++)
#pragma unroll
            for (int l = 0; l < 4; l++) R.a[i][j][l] = 0.f;

    const int wid = tid >> 5, lane = tid & 31;
    const int g = lane >> 2, tg = lane & 3;
    const int mB = (wid & 3) << 5, nB = (wid >> 2) << 5;

    float4 aR[4], wR[2];
#pragma unroll
    for (int i = 0; i < 4; i++) aR[i] = *(const float4*)(Ag + (size_t)i * 32 * lda);
#pragma unroll
    for (int i = 0; i < 2; i++) wR[i] = *(const float4*)(Wg + (size_t)i * 32 * K);

    {
        float* As = sm;
        float* Bs = sm + 128 * TFPAD;
#pragma unroll
        for (int i = 0; i < 4; i++)
            *(float4*)&As[(arow + i * 32) * TFPAD + acol] = cvt_tf32_4(aR[i]);
#pragma unroll
        for (int i = 0; i < 2; i++)
            *(float4*)&Bs[(arow + i * 32) * TFPAD + acol] = cvt_tf32_4(wR[i]);
    }
    __syncthreads();

    const int nk = K >> 5;
    for (int kc = 0; kc < nk; ++kc) {
        if (kc + 1 < nk) {
            const float* Ag2 = Ag + (kc + 1) * 32;
            const float* Wg2 = Wg + (kc + 1) * 32;
#pragma unroll
            for (int i = 0; i < 4; i++) aR[i] = *(const float4*)(Ag2 + (size_t)i * 32 * lda);
#pragma unroll
            for (int i = 0; i < 2; i++) wR[i] = *(const float4*)(Wg2 + (size_t)i * 32 * K);
        }

        const float* As = sm + (kc & 1) * TF_STAGE;
        const float* Bs = As + 128 * TFPAD;
#pragma unroll
        for (int kf = 0; kf < 4; ++kf) {
            const int kk = (kf << 3) + tg;
            unsigned a[2][4], b[4][2];
#pragma unroll
            for (int mf = 0; mf < 2; ++mf) {
                int r = mB + (mf << 4) + g;
                a[mf][0] = __float_as_uint(As[r * TFPAD + kk]);
                a[mf][1] = __float_as_uint(As[(r + 8) * TFPAD + kk]);
                a[mf][2] = __float_as_uint(As[r * TFPAD + kk + 4]);
                a[mf][3] = __float_as_uint(As[(r + 8) * TFPAD + kk + 4]);
            }
#pragma unroll
            for (int nf = 0; nf < 4; ++nf) {
                int n = nB + (nf << 3) + g;
                b[nf][0] = __float_as_uint(Bs[n * TFPAD + kk]);
                b[nf][1] = __float_as_uint(Bs[n * TFPAD + kk + 4]);
            }
#pragma unroll
            for (int mf = 0; mf < 2; ++mf)
#pragma unroll
                for (int nf = 0; nf < 4; ++nf)
                    mma_tf32(R.a[mf][nf], a[mf], b[nf]);
        }

        if (kc + 1 < nk) {
            float* Ad = sm + ((kc + 1) & 1) * TF_STAGE;
            float* Bd = Ad + 128 * TFPAD;
#pragma unroll
            for (int i = 0; i < 4; i++)
                *(float4*)&Ad[(arow + i * 32) * TFPAD + acol] = cvt_tf32_4(aR[i]);
#pragma unroll
            for (int i = 0; i < 2; i++)
                *(float4*)&Bd[(arow + i * 32) * TFPAD + acol] = cvt_tf32_4(wR[i]);
            __syncthreads();
        }
    }
}

// Standard tf32 GEMM with bias epilogue.
__global__ __launch_bounds__(256) void gemm_tf32_k(
    const float* __restrict__ A, const float* __restrict__ W,
    const float* __restrict__ bias, float* __restrict__ C,
    int K, int lda, int ldc)
{
    extern __shared__ float sm[];
    const int m0 = blockIdx.y << 7, n0 = blockIdx.x << 6;
    TFAcc R;
    tf32_mainloop(A, W, K, lda, m0, n0, sm, R);

    const int tid = threadIdx.x;
    const int wid = tid >> 5, lane = tid & 31;
    const int g = lane >> 2, tg = lane & 3;
    const int mB = (wid & 3) << 5, nB = (wid >> 2) << 5;

#pragma unroll
    for (int mf = 0; mf < 2; ++mf)
#pragma unroll
        for (int nf = 0; nf < 4; ++nf) {
            int row = m0 + mB + (mf << 4) + g;
            int col = n0 + nB + (nf << 3) + (tg << 1);
            float2 bb = make_float2(0.f, 0.f);
            if (bias) bb = *(const float2*)&bias[col];
            float2 v;
            v.x = R.a[mf][nf][0] + bb.x;
            v.y = R.a[mf][nf][1] + bb.y;
            *(float2*)&C[(size_t)row * ldc + col] = v;
            v.x = R.a[mf][nf][2] + bb.x;
            v.y = R.a[mf][nf][3] + bb.y;
            *(float2*)&C[(size_t)(row + 8) * ldc + col] = v;
        }
}

// Fused heads: tf32 GEMM (state @ Whr^T + b) -> GELU -> 64->1 dot -> out.
// grid.x selects the head (N-tile of 64 == one head).  No hdn buffer.
__global__ __launch_bounds__(256) void heads_fused_k(
    const float* __restrict__ A, const float* __restrict__ W,
    const float* __restrict__ bias,
    const float* __restrict__ Wh2, const float* __restrict__ bh2,
    const float* __restrict__ Wt2, const float* __restrict__ bt2,
    const float* __restrict__ Wv2, const float* __restrict__ bv2,
    float* __restrict__ oh, float* __restrict__ ot, float* __restrict__ ov)
{
    extern __shared__ float sm[];
    const int head = blockIdx.x;
    const int m0 = blockIdx.y << 7, n0 = head << 6;
    TFAcc R;
    tf32_mainloop(A, W, 128, 128, m0, n0, sm, R);

    const int tid = threadIdx.x;
    const int wid = tid >> 5, lane = tid & 31;
    const int g = lane >> 2, tg = lane & 3;
    const int mB = (wid & 3) << 5, nB = (wid >> 2) << 5;
    const int nw = wid >> 2;

    const float* W2 = (head == 0) ? Wh2 : (head == 1 ? Wt2 : Wv2);
    const float* b2 = (head == 0) ? bh2 : (head == 1 ? bt2 : bv2);

    const float c_isqrt2 = 0.7071067811865476f;
    float part[2][2];  // [mf][rowhalf]
#pragma unroll
    for (int mf = 0; mf < 2; ++mf) { part[mf][0] = 0.f; part[mf][1] = 0.f; }

#pragma unroll
    for (int mf = 0; mf < 2; ++mf)
#pragma unroll
        for (int nf = 0; nf < 4; ++nf) {
            int colL = nB + (nf << 3) + (tg << 1);      // local col in [0,64)
            float b0 = bias[n0 + colL], b1 = bias[n0 + colL + 1];
            float w0 = W2[colL], w1 = W2[colL + 1];
            float x0 = R.a[mf][nf][0] + b0;
            float x1 = R.a[mf][nf][1] + b1;
            float x2 = R.a[mf][nf][2] + b0;
            float x3 = R.a[mf][nf][3] + b1;
            float g0 = 0.5f * x0 * (1.f + erff(x0 * c_isqrt2));
            float g1 = 0.5f * x1 * (1.f + erff(x1 * c_isqrt2));
            float g2 = 0.5f * x2 * (1.f + erff(x2 * c_isqrt2));
            float g3 = 0.5f * x3 * (1.f + erff(x3 * c_isqrt2));
            part[mf][0] += g0 * w0 + g1 * w1;
            part[mf][1] += g2 * w0 + g3 * w1;
        }

    // reduce over tg (lanes sharing g)
#pragma unroll
    for (int mf = 0; mf < 2; ++mf)
#pragma unroll
        for (int rh = 0; rh < 2; ++rh) {
            part[mf][rh] += __shfl_xor_sync(0xffffffffu, part[mf][rh], 1);
            part[mf][rh] += __shfl_xor_sync(0xffffffffu, part[mf][rh], 2);
        }

    __syncthreads();           // done reading mainloop smem
    float* red = sm;           // [2][128]
    if (tg == 0) {
#pragma unroll
        for (int mf = 0; mf < 2; ++mf) {
            int r = mB + (mf << 4) + g;
            red[nw * 128 + r] = part[mf][0];
            red[nw * 128 + r + 8] = part[mf][1];
        }
    }
    __syncthreads();
    if (tid < 128) {
        float v = red[tid] + red[128 + tid] + b2[0];
        float* o = (head == 0) ? oh : (head == 1 ? ot : ov);
        o[m0 + tid] = v;
    }
}

// ---------------------------------------------------------------------------
// GRU scan: one CTA per (b,e) lane, 384 threads; W_hh row in registers,
// packed f32x2 FMAs, MUFU activations.
// ---------------------------------------------------------------------------
__global__ __launch_bounds__(384) void gru_k(
    const float* __restrict__ gp, const float* __restrict__ rw,
    const float* __restrict__ Whh, const float* __restrict__ b_ih,
    const float* __restrict__ b_hh, const float* __restrict__ state0,
    float* __restrict__ state_out)
{
    __shared__ __align__(16) float h_s[128];
    __shared__ float sA[384];
    __shared__ float sHn[128];

    int tid = threadIdx.x;
    int L = blockIdx.x;
    int b = L >> 3, e = L & 7;

    ulonglong2 w[32];
    const ulonglong2* Wrow = (const ulonglong2*)(Whh + (size_t)tid * 128);
#pragma unroll
    for (int j = 0; j < 32; ++j) w[j] = Wrow[j];

    if (tid < 128) h_s[tid] = state0[(e << 7) + tid];
    float bihr = b_ih[tid];
    float bhhr = b_hh[tid];
    size_t gpBase = ((size_t)b * Tc) * 384 + tid;
    size_t rwBase = ((size_t)b * Tc) * 8 + e;
    size_t soBase = (((size_t)b * Tc) * 8 + e) * 128;
    __syncthreads();

    const ulonglong2* h2 = (const ulonglong2*)h_s;
    float gpc = gp[gpBase];
    float rwc = rw[rwBase];

    for (int t = 0; t < Tc; ++t) {
        float gpn = 0.f, rwn = 0.f;
        if (t + 1 < Tc) {
            gpn = gp[gpBase + (size_t)(t + 1) * 384];
            rwn = rw[rwBase + (size_t)(t + 1) * 8];
        }
        unsigned long long acc0 = 0ull, acc1 = 0ull;
#pragma unroll
        for (int j = 0; j < 32; ++j) {
            ulonglong2 hv = h2[j];             // warp-uniform broadcast
            acc0 = ffma2(w[j].x, hv.x, acc0);
            acc1 = ffma2(w[j].y, hv.y, acc1);
        }
        float acc = lo2(acc0) + hi2(acc0) + lo2(acc1) + hi2(acc1) + bhhr;
        float gi = fmaf(rwc, gpc, bihr);
        if (tid < 256) sA[tid] = gi + acc;
        else { sA[tid] = gi; sHn[tid - 256] = acc; }
        __syncthreads();
        if (tid < 128) {
            float r = fast_sigmoid(sA[tid]);
            float z = fast_sigmoid(sA[128 + tid]);
            float n = fast_tanh(fmaf(r, sHn[tid], sA[256 + tid]));
            float hold = h_s[tid];
            float hn = fmaf(z, hold - n, n);
            h_s[tid] = hn;
            state_out[soBase + (size_t)t * 1024 + tid] = hn;
        }
        __syncthreads();
        gpc = gpn; rwc = rwn;
    }
}

// ---------------------------------------------------------------------------
// Launch — two-stream fork so weight-prep + route overlap the scan.
// ---------------------------------------------------------------------------
extern "C" void kernel_launch(void* const* d_in, const int* in_sizes, int n_in,
                              void* d_out, int out_size)
{
    const float* h_seq = (const float*)d_in[0];
    const float* keys  = (const float*)d_in[1];
    const float* state0= (const float*)d_in[2];
    const float* Wi    = (const float*)d_in[3];
    const float* bi    = (const float*)d_in[4];
    const float* W_ih  = (const float*)d_in[5];
    const float* W_hh  = (const float*)d_in[6];
    const float* b_ih  = (const float*)d_in[7];
    const float* b_hh  = (const float*)d_in[8];
    const float* Wm    = (const float*)d_in[9];
    const float* bm    = (const float*)d_in[10];
    const float* Ws    = (const float*)d_in[11];
    const float* bs    = (const float*)d_in[12];
    const float* Wh1   = (const float*)d_in[13];
    const float* bh1   = (const float*)d_in[14];
    const float* Wh2   = (const float*)d_in[15];
    const float* bh2   = (const float*)d_in[16];
    const float* Wt1   = (const float*)d_in[17];
    const float* bt1   = (const float*)d_in[18];
    const float* Wt2   = (const float*)d_in[19];
    const float* bt2   = (const float*)d_in[20];
    const float* Wv1   = (const float*)d_in[21];
    const float* bv1   = (const float*)d_in[22];
    const float* Wv2   = (const float*)d_in[23];
    const float* bv2   = (const float*)d_in[24];

    float* out = (float*)d_out;
    float* o_pooled = out;                                     // [8,1024,768]
    float* o_mem    = o_pooled + (size_t)8192 * 768;           // [8,1024,8,768]
    float* o_state  = o_mem + (size_t)65536 * 768;             // [8,1024,8,128]
    float* o_holder = o_state + (size_t)65536 * 128;           // [8,1024,8]
    float* o_tagged = o_holder + 65536;
    float* o_visib  = o_tagged + 65536;
    float* o_route  = o_visib + 65536;

    float *p_Wit, *p_Wiht, *p_Wmt, *p_Wst, *p_Whr, *p_bhcat;
    float *p_proj, *p_gp, *p_Cp, *p_Cpt, *p_bpool;
    cudaGetSymbolAddress((void**)&p_Wit,   g_Wit);
    cudaGetSymbolAddress((void**)&p_Wiht,  g_Wiht);
    cudaGetSymbolAddress((void**)&p_Wmt,   g_Wmt);
    cudaGetSymbolAddress((void**)&p_Wst,   g_Wst);
    cudaGetSymbolAddress((void**)&p_Whr,   g_Whr);
    cudaGetSymbolAddress((void**)&p_bhcat, g_bhcat);
    cudaGetSymbolAddress((void**)&p_proj,  g_proj);
    cudaGetSymbolAddress((void**)&p_gp,    g_gp);
    cudaGetSymbolAddress((void**)&p_Cp,    g_Cp);
    cudaGetSymbolAddress((void**)&p_Cpt,   g_Cpt);
    cudaGetSymbolAddress((void**)&p_bpool, g_bpool);

    // One-time host-side handles (no device memory involved)
    static cudaStream_t s1 = nullptr;
    static cudaEvent_t evFork = nullptr, evRoute = nullptr, evW = nullptr;
    if (!s1) {
        cudaStreamCreateWithFlags(&s1, cudaStreamNonBlocking);
        cudaEventCreateWithFlags(&evFork, cudaEventDisableTiming);
        cudaEventCreateWithFlags(&evRoute, cudaEventDisableTiming);
        cudaEventCreateWithFlags(&evW, cudaEventDisableTiming);
    }

    const int tfsmem = 2 * TF_STAGE * 4;  // 55296 bytes
    cudaFuncSetAttribute(gemm_tf32_k, cudaFuncAttributeMaxDynamicSharedMemorySize, tfsmem);
    cudaFuncSetAttribute(heads_fused_k, cudaFuncAttributeMaxDynamicSharedMemorySize, tfsmem);

    dim3 tb(32, 8);

    // ---- fork s1 off the main (default) stream ----
    cudaEventRecord(evFork, 0);
    cudaStreamWaitEvent(s1, evFork, 0);

    // s1: route (scan dependency) then the weight-only chain (hidden by scan)
    route_k<<<1024, 256, 0, s1>>>(h_seq, keys, o_route);
    cudaEventRecord(evRoute, s1);
    transpose_k<<<dim3(4, 24),  tb, 0, s1>>>(Wm,   p_Wmt,  768, 128);
    transpose_k<<<dim3(192, 24), tb, 0, s1>>>(Ws,  p_Wst,  768, 6144);
    sgemm_k<<<dim3(12, 2, 8), 256, 0, s1>>>(p_Wmt, p_Wst, nullptr, p_Cp,
                                            128, 768, 768, 0, 589824, 98304);
    transpose_k<<<dim3(24, 32), tb, 0, s1>>>(p_Cp, p_Cpt, 1024, 768);
    bpool_k<<<768, 256, 0, s1>>>(Ws, bm, bs, p_bpool);
    headscat_k<<<96, 256, 0, s1>>>(Wh1, Wt1, Wv1, bh1, bt1, bv1, p_Whr, p_bhcat);
    cudaEventRecord(evW, s1);

    // s0: scan-feeding chain
    transpose_k<<<dim3(24, 4),  tb>>>(Wi,   p_Wit,  128, 768);
    transpose_k<<<dim3(4, 12),  tb>>>(W_ih, p_Wiht, 384, 128);
    sgemm_k<<<dim3(2, 128), 256>>>(h_seq, p_Wit, bi, p_proj, 8192, 128, 768, 0, 0, 0);
    sgemm_k<<<dim3(6, 128), 256>>>(p_proj, p_Wiht, nullptr, p_gp, 8192, 384, 128, 0, 0, 0);

    cudaStreamWaitEvent(0, evRoute, 0);
    gru_k<<<64, 384>>>(p_gp, o_route, W_hh, b_ih, b_hh, state0, o_state);

    // tails on s0 (weight chain joined via evW)
    gemm_tf32_k<<<dim3(12, 512), 256, tfsmem>>>(o_state, Wm, bm, o_mem, 128, 128, 768);
    cudaStreamWaitEvent(0, evW, 0);
    heads_fused_k<<<dim3(3, 512), 256, tfsmem>>>(o_state, p_Whr, p_bhcat,
                                                 Wh2, bh2, Wt2, bt2, Wv2, bv2,
                                                 o_holder, o_tagged, o_visib);
    gemm_tf32_k<<<dim3(12, 64), 256, tfsmem>>>(o_state, p_Cpt, p_bpool, o_pooled,
                                               1024, 1024, 768);
}

// round 6
// speedup vs baseline: 2.7461x; 1.1699x over previous
#include <cuda_runtime.h>
#include <math.h>

// Problem constants
#define Bc  8
#define Tc  1024
#define Dc  768
#define NEc 8
#define DSc 128
#define Hc  64
#define NCH 4
#define TCH (Tc / NCH)          // 256 timesteps per chunk

// ---------------------------------------------------------------------------
// Scratch (static __device__ arrays — no allocation at runtime)
// ---------------------------------------------------------------------------
__device__ float g_Wit[768 * 128];      // Wi^T            [768,128]
__device__ float g_Wiht[128 * 384];     // W_ih^T          [128,384]
__device__ float g_Wmt[128 * 768];      // Wm^T            [128,768]
__device__ float g_Wst[6144 * 768];     // Ws^T            [6144,768]
__device__ float g_Whr[192 * 128];      // [Wh1;Wt1;Wv1] row-concat [192,128]
__device__ float g_bhcat[192];
__device__ float g_proj[8192 * 128];    // h_seq @ Wi^T + bi
__device__ float g_gp[8192 * 384];      // proj @ W_ih^T (no bias)
__device__ float g_Cp[1024 * 768];      // combined pooled weight [NE*DS, D]
__device__ float g_Cpt[768 * 1024];     // Cp^T  [D, NE*DS]
__device__ float g_bpool[768];          // combined pooled bias

// ---------------------------------------------------------------------------
// Packed fp32x2 FMA (sm_100+)
// ---------------------------------------------------------------------------
__device__ __forceinline__ unsigned long long ffma2(
    unsigned long long a, unsigned long long b, unsigned long long c)
{
    unsigned long long d;
    asm("fma.rn.f32x2 %0, %1, %2, %3;" : "=l"(d) : "l"(a), "l"(b), "l"(c));
    return d;
}
__device__ __forceinline__ unsigned long long pack2(float lo, float hi)
{
    unsigned long long d;
    asm("mov.b64 %0, {%1, %2};" : "=l"(d) : "f"(lo), "f"(hi));
    return d;
}
__device__ __forceinline__ float lo2(unsigned long long v)
{ return __uint_as_float((unsigned)(v & 0xffffffffull)); }
__device__ __forceinline__ float hi2(unsigned long long v)
{ return __uint_as_float((unsigned)(v >> 32)); }

// MUFU-based activations (~1e-6 error)
__device__ __forceinline__ float fast_sigmoid(float x)
{
    float e = __expf(-x);
    float r;
    asm("rcp.approx.f32 %0, %1;" : "=f"(r) : "f"(1.0f + e));
    return r;
}
__device__ __forceinline__ float fast_tanh(float x)
{
    float e = __expf(x + x);
    float r;
    asm("rcp.approx.f32 %0, %1;" : "=f"(r) : "f"(1.0f + e));
    return fmaf(-2.0f, r, 1.0f);
}

// ---------------------------------------------------------------------------
// Generic transpose: out[C,R] = in[R,C]^T
// ---------------------------------------------------------------------------
__global__ void transpose_k(const float* __restrict__ in, float* __restrict__ out,
                            int R, int C)
{
    __shared__ float t[32][33];
    int c0 = blockIdx.x * 32, r0 = blockIdx.y * 32;
#pragma unroll
    for (int i = 0; i < 4; i++) {
        int r = r0 + threadIdx.y + i * 8;
        int c = c0 + threadIdx.x;
        if (r < R && c < C) t[threadIdx.y + i * 8][threadIdx.x] = in[(size_t)r * C + c];
    }
    __syncthreads();
#pragma unroll
    for (int i = 0; i < 4; i++) {
        int c = c0 + threadIdx.y + i * 8;
        int r = r0 + threadIdx.x;
        if (r < R && c < C) out[(size_t)c * R + r] = t[threadIdx.x][threadIdx.y + i * 8];
    }
}

// ---------------------------------------------------------------------------
// Row-concat head layer-1 weights [192,128] and biases [192]
// ---------------------------------------------------------------------------
__global__ void headscat_k(const float* __restrict__ Wh1, const float* __restrict__ Wt1,
                           const float* __restrict__ Wv1, const float* __restrict__ bh1,
                           const float* __restrict__ bt1, const float* __restrict__ bv1,
                           float* __restrict__ Wr, float* __restrict__ bcat)
{
    int idx = blockIdx.x * 256 + threadIdx.x;
    if (idx < 24576) {
        const float* src = (idx < 8192) ? Wh1 : (idx < 16384 ? Wt1 : Wv1);
        Wr[idx] = src[idx & 8191];
    }
    if (idx < 192) {
        int h = idx >> 6, n = idx & 63;
        const float* bb = (h == 0) ? bh1 : (h == 1 ? bt1 : bv1);
        bcat[idx] = bb[n];
    }
}

// ---------------------------------------------------------------------------
// Routing: logits + softmax over NE=8.  One warp per (b,t) row.
// ---------------------------------------------------------------------------
__global__ __launch_bounds__(256) void route_k(const float* __restrict__ h_seq,
                                               const float* __restrict__ keys,
                                               float* __restrict__ rw)
{
    __shared__ float4 ks[8 * 192];
    int tid = threadIdx.x;
    const float4* k4 = (const float4*)keys;
    for (int i = tid; i < 1536; i += 256) ks[i] = k4[i];
    __syncthreads();

    int r = blockIdx.x * 8 + (tid >> 5);
    int lane = tid & 31;
    const float4* h4 = (const float4*)h_seq + (size_t)r * 192;
    float acc[8];
#pragma unroll
    for (int e = 0; e < 8; e++) acc[e] = 0.f;
#pragma unroll
    for (int i = 0; i < 6; i++) {
        float4 hv = h4[i * 32 + lane];
#pragma unroll
        for (int e = 0; e < 8; e++) {
            float4 kv = ks[e * 192 + i * 32 + lane];
            acc[e] += hv.x * kv.x + hv.y * kv.y + hv.z * kv.z + hv.w * kv.w;
        }
    }
#pragma unroll
    for (int e = 0; e < 8; e++)
#pragma unroll
        for (int s = 16; s; s >>= 1) acc[e] += __shfl_xor_sync(0xffffffffu, acc[e], s);

    if (lane == 0) {
        const float inv = 1.0f / 27.712812921102035f;
        float m = -1e30f;
#pragma unroll
        for (int e = 0; e < 8; e++) { acc[e] *= inv; m = fmaxf(m, acc[e]); }
        float s = 0.f;
#pragma unroll
        for (int e = 0; e < 8; e++) { acc[e] = expf(acc[e] - m); s += acc[e]; }
        float is = 1.f / s;
#pragma unroll
        for (int e = 0; e < 8; e++) rw[(size_t)r * 8 + e] = acc[e] * is;
    }
}

// ---------------------------------------------------------------------------
// Combined pooled bias
// ---------------------------------------------------------------------------
__global__ void bpool_k(const float* __restrict__ Ws, const float* __restrict__ bm,
                        const float* __restrict__ bs, float* __restrict__ bp)
{
    __shared__ float red[256];
    int d = blockIdx.x;
    const float* row = Ws + (size_t)d * 6144;
    float acc = 0.f;
    for (int e = 0; e < 8; e++)
        for (int j = threadIdx.x; j < 768; j += 256)
            acc += row[e * 768 + j] * bm[j];
    red[threadIdx.x] = acc;
    __syncthreads();
    for (int s = 128; s; s >>= 1) {
        if (threadIdx.x < s) red[threadIdx.x] += red[threadIdx.x + s];
        __syncthreads();
    }
    if (threadIdx.x == 0) bp[d] = bs[d] + red[0];
}

// ---------------------------------------------------------------------------
// fp32 SGEMM with packed f32x2 FMAs (bit-exact fp32), z-batched.
// ---------------------------------------------------------------------------
__global__ __launch_bounds__(256) void sgemm_k(
    const float* __restrict__ A, const float* __restrict__ B,
    const float* __restrict__ bias, float* __restrict__ C,
    int M, int N, int K, long long aBS, long long bBS, long long cBS)
{
    A += (size_t)blockIdx.z * aBS;
    B += (size_t)blockIdx.z * bBS;
    C += (size_t)blockIdx.z * cBS;

    __shared__ float As[16][68];
    __shared__ __align__(16) float Bs[16][64];
    int tid = threadIdx.x;
    int m0 = blockIdx.y * 64, n0 = blockIdx.x * 64;
    int ar = tid >> 2, ac = (tid & 3) << 2;
    int br = tid >> 4, bc = (tid & 15) << 2;
    int tx = tid & 15, ty = tid >> 4;

    unsigned long long acc2[4][2];
#pragma unroll
    for (int i = 0; i < 4; i++) { acc2[i][0] = 0ull; acc2[i][1] = 0ull; }

    const float* Ap = A + (size_t)(m0 + ar) * K + ac;
    const float* Bp = B + (size_t)br * N + n0 + bc;
    int nk = K >> 4;
    float4 a4 = *(const float4*)Ap;
    float4 b4 = *(const float4*)Bp;

    for (int kt = 0; kt < nk; ++kt) {
        As[ac + 0][ar] = a4.x; As[ac + 1][ar] = a4.y;
        As[ac + 2][ar] = a4.z; As[ac + 3][ar] = a4.w;
        *(float4*)&Bs[br][bc] = b4;
        __syncthreads();
        if (kt + 1 < nk) {
            a4 = *(const float4*)(Ap + (kt + 1) * 16);
            b4 = *(const float4*)(Bp + (size_t)(kt + 1) * 16 * N);
        }
#pragma unroll
        for (int k = 0; k < 16; ++k) {
            float4 av = *(const float4*)&As[k][ty << 2];
            ulonglong2 bv = *(const ulonglong2*)&Bs[k][tx << 2];
            unsigned long long a0 = pack2(av.x, av.x);
            unsigned long long a1 = pack2(av.y, av.y);
            unsigned long long a2 = pack2(av.z, av.z);
            unsigned long long a3 = pack2(av.w, av.w);
            acc2[0][0] = ffma2(a0, bv.x, acc2[0][0]);
            acc2[0][1] = ffma2(a0, bv.y, acc2[0][1]);
            acc2[1][0] = ffma2(a1, bv.x, acc2[1][0]);
            acc2[1][1] = ffma2(a1, bv.y, acc2[1][1]);
            acc2[2][0] = ffma2(a2, bv.x, acc2[2][0]);
            acc2[2][1] = ffma2(a2, bv.y, acc2[2][1]);
            acc2[3][0] = ffma2(a3, bv.x, acc2[3][0]);
            acc2[3][1] = ffma2(a3, bv.y, acc2[3][1]);
        }
        __syncthreads();
    }

    float4 bb = make_float4(0.f, 0.f, 0.f, 0.f);
    if (bias) bb = *(const float4*)&bias[n0 + (tx << 2)];
#pragma unroll
    for (int i = 0; i < 4; i++) {
        float4 o;
        o.x = lo2(acc2[i][0]) + bb.x; o.y = hi2(acc2[i][0]) + bb.y;
        o.z = lo2(acc2[i][1]) + bb.z; o.w = hi2(acc2[i][1]) + bb.w;
        *(float4*)&C[(size_t)(m0 + (ty << 2) + i) * N + n0 + (tx << 2)] = o;
    }
}

// ---------------------------------------------------------------------------
// TF32 tensor-core GEMM helpers
// ---------------------------------------------------------------------------
__device__ __forceinline__ float4 cvt_tf32_4(float4 v)
{
    float4 r;
    asm("cvt.rna.tf32.f32 %0, %1;" : "=f"(r.x) : "f"(v.x));
    asm("cvt.rna.tf32.f32 %0, %1;" : "=f"(r.y) : "f"(v.y));
    asm("cvt.rna.tf32.f32 %0, %1;" : "=f"(r.z) : "f"(v.z));
    asm("cvt.rna.tf32.f32 %0, %1;" : "=f"(r.w) : "f"(v.w));
    return r;
}

__device__ __forceinline__ void mma_tf32(float* c, const unsigned* a, const unsigned* b)
{
    asm volatile(
        "mma.sync.aligned.m16n8k8.row.col.f32.tf32.tf32.f32 "
        "{%0,%1,%2,%3}, {%4,%5,%6,%7}, {%8,%9}, {%0,%1,%2,%3};"
        : "+f"(c[0]), "+f"(c[1]), "+f"(c[2]), "+f"(c[3])
        : "r"(a[0]), "r"(a[1]), "r"(a[2]), "r"(a[3]), "r"(b[0]), "r"(b[1]));
}

#define TFPAD 36
#define TF_STAGE (128 * TFPAD + 64 * TFPAD)   // 6912 floats per stage

struct TFAcc { float a[2][4][4]; };

__device__ __forceinline__ void tf32_mainloop(
    const float* __restrict__ A, const float* __restrict__ W,
    int K, int lda, int m0, int n0, float* sm, TFAcc& R)
{
    const int tid = threadIdx.x;
    const int arow = tid >> 3, acol = (tid & 7) << 2;
    const float* Ag = A + (size_t)(m0 + arow) * lda + acol;
    const float* Wg = W + (size_t)(n0 + arow) * K + acol;

#pragma unroll
    for (int i = 0; i < 2; i++)
#pragma unroll
        for (int j = 0; j < 4; j++)
#pragma unroll
            for (int l = 0; l < 4; l++) R.a[i][j][l] = 0.f;

    const int wid = tid >> 5, lane = tid & 31;
    const int g = lane >> 2, tg = lane & 3;
    const int mB = (wid & 3) << 5, nB = (wid >> 2) << 5;

    float4 aR[4], wR[2];
#pragma unroll
    for (int i = 0; i < 4; i++) aR[i] = *(const float4*)(Ag + (size_t)i * 32 * lda);
#pragma unroll
    for (int i = 0; i < 2; i++) wR[i] = *(const float4*)(Wg + (size_t)i * 32 * K);

    {
        float* As = sm;
        float* Bs = sm + 128 * TFPAD;
#pragma unroll
        for (int i = 0; i < 4; i++)
            *(float4*)&As[(arow + i * 32) * TFPAD + acol] = cvt_tf32_4(aR[i]);
#pragma unroll
        for (int i = 0; i < 2; i++)
            *(float4*)&Bs[(arow + i * 32) * TFPAD + acol] = cvt_tf32_4(wR[i]);
    }
    __syncthreads();

    const int nk = K >> 5;
    for (int kc = 0; kc < nk; ++kc) {
        if (kc + 1 < nk) {
            const float* Ag2 = Ag + (kc + 1) * 32;
            const float* Wg2 = Wg + (kc + 1) * 32;
#pragma unroll
            for (int i = 0; i < 4; i++) aR[i] = *(const float4*)(Ag2 + (size_t)i * 32 * lda);
#pragma unroll
            for (int i = 0; i < 2; i++) wR[i] = *(const float4*)(Wg2 + (size_t)i * 32 * K);
        }

        const float* As = sm + (kc & 1) * TF_STAGE;
        const float* Bs = As + 128 * TFPAD;
#pragma unroll
        for (int kf = 0; kf < 4; ++kf) {
            const int kk = (kf << 3) + tg;
            unsigned a[2][4], b[4][2];
#pragma unroll
            for (int mf = 0; mf < 2; ++mf) {
                int r = mB + (mf << 4) + g;
                a[mf][0] = __float_as_uint(As[r * TFPAD + kk]);
                a[mf][1] = __float_as_uint(As[(r + 8) * TFPAD + kk]);
                a[mf][2] = __float_as_uint(As[r * TFPAD + kk + 4]);
                a[mf][3] = __float_as_uint(As[(r + 8) * TFPAD + kk + 4]);
            }
#pragma unroll
            for (int nf = 0; nf < 4; ++nf) {
                int n = nB + (nf << 3) + g;
                b[nf][0] = __float_as_uint(Bs[n * TFPAD + kk]);
                b[nf][1] = __float_as_uint(Bs[n * TFPAD + kk + 4]);
            }
#pragma unroll
            for (int mf = 0; mf < 2; ++mf)
#pragma unroll
                for (int nf = 0; nf < 4; ++nf)
                    mma_tf32(R.a[mf][nf], a[mf], b[nf]);
        }

        if (kc + 1 < nk) {
            float* Ad = sm + ((kc + 1) & 1) * TF_STAGE;
            float* Bd = Ad + 128 * TFPAD;
#pragma unroll
            for (int i = 0; i < 4; i++)
                *(float4*)&Ad[(arow + i * 32) * TFPAD + acol] = cvt_tf32_4(aR[i]);
#pragma unroll
            for (int i = 0; i < 2; i++)
                *(float4*)&Bd[(arow + i * 32) * TFPAD + acol] = cvt_tf32_4(wR[i]);
            __syncthreads();
        }
    }
}

// Standard tf32 GEMM with bias epilogue, z-batched.
__global__ __launch_bounds__(256) void gemm_tf32_k(
    const float* __restrict__ A, const float* __restrict__ W,
    const float* __restrict__ bias, float* __restrict__ C,
    int K, int lda, int ldc, long long aOff, long long cOff)
{
    extern __shared__ float sm[];
    A += (size_t)blockIdx.z * aOff;
    C += (size_t)blockIdx.z * cOff;
    const int m0 = blockIdx.y << 7, n0 = blockIdx.x << 6;
    TFAcc R;
    tf32_mainloop(A, W, K, lda, m0, n0, sm, R);

    const int tid = threadIdx.x;
    const int wid = tid >> 5, lane = tid & 31;
    const int g = lane >> 2, tg = lane & 3;
    const int mB = (wid & 3) << 5, nB = (wid >> 2) << 5;

#pragma unroll
    for (int mf = 0; mf < 2; ++mf)
#pragma unroll
        for (int nf = 0; nf < 4; ++nf) {
            int row = m0 + mB + (mf << 4) + g;
            int col = n0 + nB + (nf << 3) + (tg << 1);
            float2 bb = make_float2(0.f, 0.f);
            if (bias) bb = *(const float2*)&bias[col];
            float2 v;
            v.x = R.a[mf][nf][0] + bb.x;
            v.y = R.a[mf][nf][1] + bb.y;
            *(float2*)&C[(size_t)row * ldc + col] = v;
            v.x = R.a[mf][nf][2] + bb.x;
            v.y = R.a[mf][nf][3] + bb.y;
            *(float2*)&C[(size_t)(row + 8) * ldc + col] = v;
        }
}

// Fused heads: tf32 GEMM -> GELU -> 64->1 dot -> out.  z-batched.
__global__ __launch_bounds__(256) void heads_fused_k(
    const float* __restrict__ A, const float* __restrict__ W,
    const float* __restrict__ bias,
    const float* __restrict__ Wh2, const float* __restrict__ bh2,
    const float* __restrict__ Wt2, const float* __restrict__ bt2,
    const float* __restrict__ Wv2, const float* __restrict__ bv2,
    float* __restrict__ oh, float* __restrict__ ot, float* __restrict__ ov,
    long long aOff, long long oOff)
{
    extern __shared__ float sm[];
    A += (size_t)blockIdx.z * aOff;
    const int head = blockIdx.x;
    const int m0 = blockIdx.y << 7, n0 = head << 6;
    TFAcc R;
    tf32_mainloop(A, W, 128, 128, m0, n0, sm, R);

    const int tid = threadIdx.x;
    const int wid = tid >> 5, lane = tid & 31;
    const int g = lane >> 2, tg = lane & 3;
    const int mB = (wid & 3) << 5, nB = (wid >> 2) << 5;
    const int nw = wid >> 2;

    const float* W2 = (head == 0) ? Wh2 : (head == 1 ? Wt2 : Wv2);
    const float* b2 = (head == 0) ? bh2 : (head == 1 ? bt2 : bv2);

    const float c_isqrt2 = 0.7071067811865476f;
    float part[2][2];
#pragma unroll
    for (int mf = 0; mf < 2; ++mf) { part[mf][0] = 0.f; part[mf][1] = 0.f; }

#pragma unroll
    for (int mf = 0; mf < 2; ++mf)
#pragma unroll
        for (int nf = 0; nf < 4; ++nf) {
            int colL = nB + (nf << 3) + (tg << 1);
            float b0 = bias[n0 + colL], b1 = bias[n0 + colL + 1];
            float w0 = W2[colL], w1 = W2[colL + 1];
            float x0 = R.a[mf][nf][0] + b0;
            float x1 = R.a[mf][nf][1] + b1;
            float x2 = R.a[mf][nf][2] + b0;
            float x3 = R.a[mf][nf][3] + b1;
            float g0 = 0.5f * x0 * (1.f + erff(x0 * c_isqrt2));
            float g1 = 0.5f * x1 * (1.f + erff(x1 * c_isqrt2));
            float g2 = 0.5f * x2 * (1.f + erff(x2 * c_isqrt2));
            float g3 = 0.5f * x3 * (1.f + erff(x3 * c_isqrt2));
            part[mf][0] += g0 * w0 + g1 * w1;
            part[mf][1] += g2 * w0 + g3 * w1;
        }

#pragma unroll
    for (int mf = 0; mf < 2; ++mf)
#pragma unroll
        for (int rh = 0; rh < 2; ++rh) {
            part[mf][rh] += __shfl_xor_sync(0xffffffffu, part[mf][rh], 1);
            part[mf][rh] += __shfl_xor_sync(0xffffffffu, part[mf][rh], 2);
        }

    __syncthreads();
    float* red = sm;
    if (tg == 0) {
#pragma unroll
        for (int mf = 0; mf < 2; ++mf) {
            int r = mB + (mf << 4) + g;
            red[nw * 128 + r] = part[mf][0];
            red[nw * 128 + r + 8] = part[mf][1];
        }
    }
    __syncthreads();
    if (tid < 128) {
        float v = red[tid] + red[128 + tid] + b2[0];
        float* o = (head == 0) ? oh : (head == 1 ? ot : ov);
        o[(size_t)blockIdx.z * oOff + m0 + tid] = v;
    }
}

// ---------------------------------------------------------------------------
// GRU scan chunk [t0,t1): one CTA per (b,e) lane, 384 threads.
// W_hh row in registers, packed f32x2 FMAs, MUFU activations.
// Chunk c>0 reloads h from state_out[t0-1].
// ---------------------------------------------------------------------------
__global__ __launch_bounds__(384) void gru_k(
    const float* __restrict__ gp, const float* __restrict__ rw,
    const float* __restrict__ Whh, const float* __restrict__ b_ih,
    const float* __restrict__ b_hh, const float* __restrict__ state0,
    float* __restrict__ state_out, int t0, int t1)
{
    __shared__ __align__(16) float h_s[128];
    __shared__ float sA[384];
    __shared__ float sHn[128];

    int tid = threadIdx.x;
    int L = blockIdx.x;
    int b = L >> 3, e = L & 7;

    ulonglong2 w[32];
    const ulonglong2* Wrow = (const ulonglong2*)(Whh + (size_t)tid * 128);
#pragma unroll
    for (int j = 0; j < 32; ++j) w[j] = Wrow[j];

    size_t gpBase = ((size_t)b * Tc) * 384 + tid;
    size_t rwBase = ((size_t)b * Tc) * 8 + e;
    size_t soBase = (((size_t)b * Tc) * 8 + e) * 128;

    if (tid < 128) {
        h_s[tid] = (t0 == 0) ? state0[(e << 7) + tid]
                             : state_out[soBase + (size_t)(t0 - 1) * 1024 + tid];
    }
    float bihr = b_ih[tid];
    float bhhr = b_hh[tid];
    __syncthreads();

    const ulonglong2* h2 = (const ulonglong2*)h_s;
    float gpc = gp[gpBase + (size_t)t0 * 384];
    float rwc = rw[rwBase + (size_t)t0 * 8];

    for (int t = t0; t < t1; ++t) {
        float gpn = 0.f, rwn = 0.f;
        if (t + 1 < t1) {
            gpn = gp[gpBase + (size_t)(t + 1) * 384];
            rwn = rw[rwBase + (size_t)(t + 1) * 8];
        }
        unsigned long long acc0 = 0ull, acc1 = 0ull;
#pragma unroll
        for (int j = 0; j < 32; ++j) {
            ulonglong2 hv = h2[j];
            acc0 = ffma2(w[j].x, hv.x, acc0);
            acc1 = ffma2(w[j].y, hv.y, acc1);
        }
        float acc = lo2(acc0) + hi2(acc0) + lo2(acc1) + hi2(acc1) + bhhr;
        float gi = fmaf(rwc, gpc, bihr);
        if (tid < 256) sA[tid] = gi + acc;
        else { sA[tid] = gi; sHn[tid - 256] = acc; }
        __syncthreads();
        if (tid < 128) {
            float r = fast_sigmoid(sA[tid]);
            float z = fast_sigmoid(sA[128 + tid]);
            float n = fast_tanh(fmaf(r, sHn[tid], sA[256 + tid]));
            float hold = h_s[tid];
            float hn = fmaf(z, hold - n, n);
            h_s[tid] = hn;
            state_out[soBase + (size_t)t * 1024 + tid] = hn;
        }
        __syncthreads();
        gpc = gpn; rwc = rwn;
    }
}

// ---------------------------------------------------------------------------
// Launch — 3-stream chunked pipeline: front(s2) -> scan(s0) -> tails(s1)
// ---------------------------------------------------------------------------
extern "C" void kernel_launch(void* const* d_in, const int* in_sizes, int n_in,
                              void* d_out, int out_size)
{
    const float* h_seq = (const float*)d_in[0];
    const float* keys  = (const float*)d_in[1];
    const float* state0= (const float*)d_in[2];
    const float* Wi    = (const float*)d_in[3];
    const float* bi    = (const float*)d_in[4];
    const float* W_ih  = (const float*)d_in[5];
    const float* W_hh  = (const float*)d_in[6];
    const float* b_ih  = (const float*)d_in[7];
    const float* b_hh  = (const float*)d_in[8];
    const float* Wm    = (const float*)d_in[9];
    const float* bm    = (const float*)d_in[10];
    const float* Ws    = (const float*)d_in[11];
    const float* bs    = (const float*)d_in[12];
    const float* Wh1   = (const float*)d_in[13];
    const float* bh1   = (const float*)d_in[14];
    const float* Wh2   = (const float*)d_in[15];
    const float* bh2   = (const float*)d_in[16];
    const float* Wt1   = (const float*)d_in[17];
    const float* bt1   = (const float*)d_in[18];
    const float* Wt2   = (const float*)d_in[19];
    const float* bt2   = (const float*)d_in[20];
    const float* Wv1   = (const float*)d_in[21];
    const float* bv1   = (const float*)d_in[22];
    const float* Wv2   = (const float*)d_in[23];
    const float* bv2   = (const float*)d_in[24];

    float* out = (float*)d_out;
    float* o_pooled = out;                                     // [8,1024,768]
    float* o_mem    = o_pooled + (size_t)8192 * 768;           // [8,1024,8,768]
    float* o_state  = o_mem + (size_t)65536 * 768;             // [8,1024,8,128]
    float* o_holder = o_state + (size_t)65536 * 128;           // [8,1024,8]
    float* o_tagged = o_holder + 65536;
    float* o_visib  = o_tagged + 65536;
    float* o_route  = o_visib + 65536;

    float *p_Wit, *p_Wiht, *p_Wmt, *p_Wst, *p_Whr, *p_bhcat;
    float *p_proj, *p_gp, *p_Cp, *p_Cpt, *p_bpool;
    cudaGetSymbolAddress((void**)&p_Wit,   g_Wit);
    cudaGetSymbolAddress((void**)&p_Wiht,  g_Wiht);
    cudaGetSymbolAddress((void**)&p_Wmt,   g_Wmt);
    cudaGetSymbolAddress((void**)&p_Wst,   g_Wst);
    cudaGetSymbolAddress((void**)&p_Whr,   g_Whr);
    cudaGetSymbolAddress((void**)&p_bhcat, g_bhcat);
    cudaGetSymbolAddress((void**)&p_proj,  g_proj);
    cudaGetSymbolAddress((void**)&p_gp,    g_gp);
    cudaGetSymbolAddress((void**)&p_Cp,    g_Cp);
    cudaGetSymbolAddress((void**)&p_Cpt,   g_Cpt);
    cudaGetSymbolAddress((void**)&p_bpool, g_bpool);

    // One-time host-side handles
    static cudaStream_t s1 = nullptr, s2 = nullptr;
    static cudaEvent_t evFork = nullptr, evRoute = nullptr, evT = nullptr;
    static cudaEvent_t evG[NCH], evC[NCH];
    if (!s1) {
        int loPri, hiPri;
        cudaDeviceGetStreamPriorityRange(&loPri, &hiPri);
        cudaStreamCreateWithPriority(&s1, cudaStreamNonBlocking, loPri);
        cudaStreamCreateWithPriority(&s2, cudaStreamNonBlocking, loPri);
        cudaEventCreateWithFlags(&evFork, cudaEventDisableTiming);
        cudaEventCreateWithFlags(&evRoute, cudaEventDisableTiming);
        cudaEventCreateWithFlags(&evT, cudaEventDisableTiming);
        for (int c = 0; c < NCH; c++) {
            cudaEventCreateWithFlags(&evG[c], cudaEventDisableTiming);
            cudaEventCreateWithFlags(&evC[c], cudaEventDisableTiming);
        }
    }

    const int tfsmem = 2 * TF_STAGE * 4;  // 55296 bytes
    cudaFuncSetAttribute(gemm_tf32_k, cudaFuncAttributeMaxDynamicSharedMemorySize, tfsmem);
    cudaFuncSetAttribute(heads_fused_k, cudaFuncAttributeMaxDynamicSharedMemorySize, tfsmem);

    dim3 tb(32, 8);

    // ---- fork s1, s2 off the capture stream ----
    cudaEventRecord(evFork, 0);
    cudaStreamWaitEvent(s1, evFork, 0);
    cudaStreamWaitEvent(s2, evFork, 0);

    // s1: route first (scan dependency), then weight-only chain, then tails.
    route_k<<<1024, 256, 0, s1>>>(h_seq, keys, o_route);
    cudaEventRecord(evRoute, s1);
    transpose_k<<<dim3(4, 24),  tb, 0, s1>>>(Wm,   p_Wmt,  768, 128);
    transpose_k<<<dim3(192, 24), tb, 0, s1>>>(Ws,  p_Wst,  768, 6144);
    sgemm_k<<<dim3(12, 2, 8), 256, 0, s1>>>(p_Wmt, p_Wst, nullptr, p_Cp,
                                            128, 768, 768, 0, 589824, 98304);
    transpose_k<<<dim3(24, 32), tb, 0, s1>>>(p_Cp, p_Cpt, 1024, 768);
    bpool_k<<<768, 256, 0, s1>>>(Ws, bm, bs, p_bpool);
    headscat_k<<<96, 256, 0, s1>>>(Wh1, Wt1, Wv1, bh1, bt1, bv1, p_Whr, p_bhcat);

    // s2: weight transposes for front GEMMs, then chunked proj/gp.
    transpose_k<<<dim3(24, 4),  tb, 0, s2>>>(Wi,   p_Wit,  128, 768);
    transpose_k<<<dim3(4, 12),  tb, 0, s2>>>(W_ih, p_Wiht, 384, 128);
    for (int c = 0; c < NCH; c++) {
        // proj chunk: rows t in [c*256,(c+1)*256) for each b (z-batch)
        sgemm_k<<<dim3(2, TCH / 64, 8), 256, 0, s2>>>(
            h_seq + (size_t)c * TCH * 768, p_Wit, bi,
            p_proj + (size_t)c * TCH * 128,
            TCH, 128, 768, (long long)Tc * 768, 0, (long long)Tc * 128);
        // gp chunk
        sgemm_k<<<dim3(6, TCH / 64, 8), 256, 0, s2>>>(
            p_proj + (size_t)c * TCH * 128, p_Wiht, nullptr,
            p_gp + (size_t)c * TCH * 384,
            TCH, 384, 128, (long long)Tc * 128, 0, (long long)Tc * 384);
        cudaEventRecord(evG[c], s2);
    }

    // s0: chunked scan
    cudaStreamWaitEvent(0, evRoute, 0);
    for (int c = 0; c < NCH; c++) {
        cudaStreamWaitEvent(0, evG[c], 0);
        gru_k<<<64, 384>>>(p_gp, o_route, W_hh, b_ih, b_hh, state0, o_state,
                           c * TCH, (c + 1) * TCH);
        cudaEventRecord(evC[c], 0);
    }

    // s1: chunked tails (after weight chain, gated per chunk on scan progress)
    const long long stB = (long long)8192 * 128;   // state rows per b
    for (int c = 0; c < NCH; c++) {
        cudaStreamWaitEvent(s1, evC[c], 0);
        const float* Ast = o_state + (size_t)c * TCH * 8 * 128;  // rows t0*8 within each b
        // memory_stack chunk: [2048 rows x 768] per b
        gemm_tf32_k<<<dim3(12, TCH * 8 / 128, 8), 256, tfsmem, s1>>>(
            Ast, Wm, bm, o_mem + (size_t)c * TCH * 8 * 768,
            128, 128, 768, stB, (long long)8192 * 768);
        // heads chunk
        heads_fused_k<<<dim3(3, TCH * 8 / 128, 8), 256, tfsmem, s1>>>(
            Ast, p_Whr, p_bhcat, Wh2, bh2, Wt2, bt2, Wv2, bv2,
            o_holder + (size_t)c * TCH * 8,
            o_tagged + (size_t)c * TCH * 8,
            o_visib + (size_t)c * TCH * 8,
            stB, 8192);
        // pooled chunk: A viewed as [1024 rows x 1024] per b
        gemm_tf32_k<<<dim3(12, TCH / 128, 8), 256, tfsmem, s1>>>(
            o_state + (size_t)c * TCH * 1024, p_Cpt, p_bpool,
            o_pooled + (size_t)c * TCH * 768,
            1024, 1024, 768, (long long)Tc * 1024, (long long)Tc * 768);
    }
    cudaEventRecord(evT, s1);
    cudaStreamWaitEvent(0, evT, 0);
}